// round 2
// baseline (speedup 1.0000x reference)
#include <cuda_runtime.h>
#include <math.h>

#define BATCH 8
#define CIN   256
#define CI    128
#define NPOS  4096

// ---------------- scratch (allocation-free: __device__ globals) ----------------
__device__ float g_TH[(size_t)BATCH * CI * NPOS];    // theta(x)  [b][k][n]
__device__ float g_PH[(size_t)BATCH * CI * NPOS];    // phi(x)    [b][k][n]
__device__ float g_GX[(size_t)BATCH * CI * NPOS];    // g(x)      [b][k][n]
__device__ float g_WY[(size_t)BATCH * CIN * NPOS];   // W(y)      [b][o][n]
__device__ float g_mean[CIN];
__device__ float g_rstd[CIN];

// =================================================================
// K1: fused projection GEMM. Out[o,n] = sum_c w[o][c] * x[b][c][n] + bias
// 384 output rows (theta 0-127, phi 128-255, g 256-383), tiles 64x128, BK=16.
// =================================================================
__global__ __launch_bounds__(256) void proj_kernel(
    const float* __restrict__ x,
    const float* __restrict__ g_w,  const float* __restrict__ g_b,
    const float* __restrict__ th_w, const float* __restrict__ th_b,
    const float* __restrict__ ph_w, const float* __restrict__ ph_b)
{
    __shared__ float As[16][68];    // weight tile, transposed [c][o]
    __shared__ float Bs[16][128];   // x tile [c][n]

    const int t    = threadIdx.x;
    const int b    = blockIdx.z;
    const int oblk = blockIdx.y;          // 0..5
    const int n0   = blockIdx.x * 128;
    const int which = oblk >> 1;          // 0 theta, 1 phi, 2 g
    const int o0    = (oblk & 1) * 64;

    const float* wsrc; const float* bsrc; float* dst;
    if (which == 0)      { wsrc = th_w; bsrc = th_b; dst = g_TH; }
    else if (which == 1) { wsrc = ph_w; bsrc = ph_b; dst = g_PH; }
    else                 { wsrc = g_w;  bsrc = g_b;  dst = g_GX; }

    const int u = t & 15;     // o sub-tile
    const int v = t >> 4;     // n sub-tile
    const float* xb = x + (size_t)b * CIN * NPOS;

    float acc[4][8];
    #pragma unroll
    for (int i = 0; i < 4; i++)
        #pragma unroll
        for (int j = 0; j < 8; j++) acc[i][j] = 0.f;

    for (int k0 = 0; k0 < CIN; k0 += 16) {
        __syncthreads();
        {   // A: [64 o][16 c] -> As[c][o]
            int o  = t >> 2;
            int cg = (t & 3) * 4;
            float4 w4 = *(const float4*)&wsrc[(size_t)(o0 + o) * CIN + k0 + cg];
            As[cg + 0][o] = w4.x; As[cg + 1][o] = w4.y;
            As[cg + 2][o] = w4.z; As[cg + 3][o] = w4.w;
        }
        #pragma unroll
        for (int i = 0; i < 2; i++) {   // B: [16 c][128 n]
            int fidx = i * 256 + t;
            int r    = fidx >> 5;
            int c4   = (fidx & 31) * 4;
            *(float4*)&Bs[r][c4] = *(const float4*)&xb[(size_t)(k0 + r) * NPOS + n0 + c4];
        }
        __syncthreads();
        #pragma unroll
        for (int k = 0; k < 16; k++) {
            float4 a  = *(const float4*)&As[k][4 * u];
            float4 b0 = *(const float4*)&Bs[k][8 * v];
            float4 b1 = *(const float4*)&Bs[k][8 * v + 4];
            float av[4] = {a.x, a.y, a.z, a.w};
            float bv[8] = {b0.x, b0.y, b0.z, b0.w, b1.x, b1.y, b1.z, b1.w};
            #pragma unroll
            for (int i = 0; i < 4; i++)
                #pragma unroll
                for (int j = 0; j < 8; j++) acc[i][j] += av[i] * bv[j];
        }
    }

    #pragma unroll
    for (int i = 0; i < 4; i++) {
        int o = o0 + 4 * u + i;
        float bias = bsrc[o];
        float* drow = dst + ((size_t)b * CI + o) * NPOS + n0 + 8 * v;
        float4 r0 = make_float4(acc[i][0] + bias, acc[i][1] + bias, acc[i][2] + bias, acc[i][3] + bias);
        float4 r1 = make_float4(acc[i][4] + bias, acc[i][5] + bias, acc[i][6] + bias, acc[i][7] + bias);
        *(float4*)&drow[0] = r0;
        *(float4*)&drow[4] = r1;
    }
}

// =================================================================
// K2: flash attention (fp32, online softmax) + fused W-conv epilogue.
// Per block: batch b, 64 queries. Loop over 64-key tiles.
// Threads 256 as (tx=t&15, ty=t>>4); S tile 4q x 4m per thread;
// Y acc: 4 queries x 8 channels per thread.
// =================================================================
#define OFF_Q 0          // Qs[128][64]
#define OFF_K 8192       // Ks[128][64]  (Pt[64][68] aliases this region)
#define OFF_P 8192
#define OFF_G 16384      // Gs[64][132]  (transposed: [j][c])
#define SMEM_F 24832     // total floats (99328 bytes)
#define OFF_Y 0          // phase 2: Ys[128][68]
#define OFF_W 8704       // phase 2: Wst[128][68]

__global__ __launch_bounds__(256, 2) void attn_kernel(
    const float* __restrict__ W_w, const float* __restrict__ W_b)
{
    extern __shared__ float sm[];
    const int t  = threadIdx.x;
    const int tx = t & 15;
    const int ty = t >> 4;
    const int b  = blockIdx.y;
    const int q0 = blockIdx.x * 64;

    const float* TH = g_TH + (size_t)b * CI * NPOS;
    const float* PH = g_PH + (size_t)b * CI * NPOS;
    const float* GX = g_GX + (size_t)b * CI * NPOS;

    // load Q tile: Qs[k][i] = TH[k][q0+i]  (128x64 floats = 2048 float4 -> 8 iters)
    #pragma unroll
    for (int i = 0; i < 8; i++) {
        int fidx = i * 256 + t;
        int k    = fidx >> 4;
        int j4   = (fidx & 15) * 4;
        *(float4*)&sm[OFF_Q + k * 64 + j4] = *(const float4*)&TH[(size_t)k * NPOS + q0 + j4];
    }

    float acc[4][8];
    #pragma unroll
    for (int i = 0; i < 4; i++)
        #pragma unroll
        for (int c = 0; c < 8; c++) acc[i][c] = 0.f;
    float mi[4], li[4];
    #pragma unroll
    for (int i = 0; i < 4; i++) { mi[i] = -INFINITY; li[i] = 0.f; }

    for (int mt = 0; mt < NPOS / 64; ++mt) {
        const int m0 = mt * 64;
        __syncthreads();   // previous PV done with Pt(=Ks region) and Gs

        #pragma unroll
        for (int i = 0; i < 8; i++) {   // Ks[k][j] = PH[k][m0+j] (128x64 -> 8 iters)
            int fidx = i * 256 + t;
            int k    = fidx >> 4;
            int j4   = (fidx & 15) * 4;
            *(float4*)&sm[OFF_K + k * 64 + j4] = *(const float4*)&PH[(size_t)k * NPOS + m0 + j4];
        }
        #pragma unroll
        for (int i = 0; i < 8; i++) {   // Gs[j][c] = GX[c][m0+j]  (transpose)
            int fidx = i * 256 + t;
            int c    = fidx >> 4;
            int j4   = (fidx & 15) * 4;
            float4 v = *(const float4*)&GX[(size_t)c * NPOS + m0 + j4];
            sm[OFF_G + (j4 + 0) * 132 + c] = v.x;
            sm[OFF_G + (j4 + 1) * 132 + c] = v.y;
            sm[OFF_G + (j4 + 2) * 132 + c] = v.z;
            sm[OFF_G + (j4 + 3) * 132 + c] = v.w;
        }
        __syncthreads();

        // ---- QK: s[iq][jm] = sum_k Q[k][4ty+iq] * K[k][4tx+jm]
        float s[4][4];
        #pragma unroll
        for (int i = 0; i < 4; i++)
            #pragma unroll
            for (int j = 0; j < 4; j++) s[i][j] = 0.f;
        #pragma unroll 4
        for (int k = 0; k < 128; k++) {
            float4 a  = *(const float4*)&sm[OFF_Q + k * 64 + 4 * ty];
            float4 bb = *(const float4*)&sm[OFF_K + k * 64 + 4 * tx];
            float av[4] = {a.x, a.y, a.z, a.w};
            float bv[4] = {bb.x, bb.y, bb.z, bb.w};
            #pragma unroll
            for (int i = 0; i < 4; i++)
                #pragma unroll
                for (int j = 0; j < 4; j++) s[i][j] += av[i] * bv[j];
        }

        // ---- online softmax (rows reduce across the 16 tx lanes)
        #pragma unroll
        for (int i = 0; i < 4; i++) {
            float mx = fmaxf(fmaxf(s[i][0], s[i][1]), fmaxf(s[i][2], s[i][3]));
            #pragma unroll
            for (int off = 8; off >= 1; off >>= 1)
                mx = fmaxf(mx, __shfl_xor_sync(0xffffffffu, mx, off));
            float mnew = fmaxf(mi[i], mx);
            float al   = __expf(mi[i] - mnew);
            mi[i] = mnew;
            float sum = 0.f;
            #pragma unroll
            for (int j = 0; j < 4; j++) { s[i][j] = __expf(s[i][j] - mnew); sum += s[i][j]; }
            #pragma unroll
            for (int off = 8; off >= 1; off >>= 1)
                sum += __shfl_xor_sync(0xffffffffu, sum, off);
            li[i] = li[i] * al + sum;
            #pragma unroll
            for (int c = 0; c < 8; c++) acc[i][c] *= al;
        }

        __syncthreads();   // all QK reads of Ks done; safe to alias with Pt
        #pragma unroll
        for (int jj = 0; jj < 4; jj++) {   // Pt[j][i] (transposed P)
            float4 pv = make_float4(s[0][jj], s[1][jj], s[2][jj], s[3][jj]);
            *(float4*)&sm[OFF_P + (4 * tx + jj) * 68 + 4 * ty] = pv;
        }
        __syncthreads();

        // ---- PV: acc[iq][cc] += sum_j P[4ty+iq][j] * G[8tx+cc][j]
        #pragma unroll 2
        for (int j = 0; j < 64; j++) {
            float4 p4 = *(const float4*)&sm[OFF_P + j * 68 + 4 * ty];
            float4 g0 = *(const float4*)&sm[OFF_G + j * 132 + 8 * tx];
            float4 g1 = *(const float4*)&sm[OFF_G + j * 132 + 8 * tx + 4];
            float pv[4] = {p4.x, p4.y, p4.z, p4.w};
            float gv[8] = {g0.x, g0.y, g0.z, g0.w, g1.x, g1.y, g1.z, g1.w};
            #pragma unroll
            for (int i = 0; i < 4; i++)
                #pragma unroll
                for (int c = 0; c < 8; c++) acc[i][c] += pv[i] * gv[c];
        }
    }

    // ================= epilogue: normalize, then WY = W_w @ Y + W_b =================
    __syncthreads();   // everything in phase-1 smem is dead now
    float rl[4];
    #pragma unroll
    for (int i = 0; i < 4; i++) rl[i] = 1.f / li[i];
    #pragma unroll
    for (int c = 0; c < 8; c++) {   // Ys[ch][q], stride 68
        float4 yv = make_float4(acc[0][c] * rl[0], acc[1][c] * rl[1],
                                acc[2][c] * rl[2], acc[3][c] * rl[3]);
        *(float4*)&sm[OFF_Y + (8 * tx + c) * 68 + 4 * ty] = yv;
    }

    float* WYb = g_WY + (size_t)b * CIN * NPOS;
    for (int oo = 0; oo < 4; oo++) {
        __syncthreads();   // Ys visible (first iter) / Wst free (later iters)
        {   // Wst[c][ol] = W_w[oo*64+ol][c]  (transpose stage)
            int ol = t >> 2;
            int cg = (t & 3) * 32;
            #pragma unroll
            for (int i = 0; i < 8; i++) {
                float4 w4 = *(const float4*)&W_w[(size_t)(oo * 64 + ol) * CI + cg + 4 * i];
                sm[OFF_W + (cg + 4 * i + 0) * 68 + ol] = w4.x;
                sm[OFF_W + (cg + 4 * i + 1) * 68 + ol] = w4.y;
                sm[OFF_W + (cg + 4 * i + 2) * 68 + ol] = w4.z;
                sm[OFF_W + (cg + 4 * i + 3) * 68 + ol] = w4.w;
            }
        }
        __syncthreads();
        float wy[4][4];
        #pragma unroll
        for (int i = 0; i < 4; i++)
            #pragma unroll
            for (int j = 0; j < 4; j++) wy[i][j] = 0.f;
        #pragma unroll 4
        for (int c = 0; c < CI; c++) {
            float4 wf = *(const float4*)&sm[OFF_W + c * 68 + 4 * tx];
            float4 yf = *(const float4*)&sm[OFF_Y + c * 68 + 4 * ty];
            float wv[4] = {wf.x, wf.y, wf.z, wf.w};
            float yv[4] = {yf.x, yf.y, yf.z, yf.w};
            #pragma unroll
            for (int io = 0; io < 4; io++)
                #pragma unroll
                for (int iq = 0; iq < 4; iq++) wy[io][iq] += wv[io] * yv[iq];
        }
        #pragma unroll
        for (int io = 0; io < 4; io++) {
            int o = oo * 64 + 4 * tx + io;
            float bias = W_b[o];
            float4 outv = make_float4(wy[io][0] + bias, wy[io][1] + bias,
                                      wy[io][2] + bias, wy[io][3] + bias);
            *(float4*)&WYb[(size_t)o * NPOS + q0 + 4 * ty] = outv;
        }
    }
}

// =================================================================
// K3: per-channel BN statistics over (B, N) — deterministic block reduce
// =================================================================
__global__ __launch_bounds__(256) void stats_kernel()
{
    const int c = blockIdx.x;
    const int t = threadIdx.x;
    float s = 0.f, ss = 0.f;
    for (int b = 0; b < BATCH; b++) {
        const float* p = g_WY + ((size_t)b * CIN + c) * NPOS;
        for (int i = t; i < NPOS / 4; i += 256) {
            float4 v = *(const float4*)&p[4 * i];
            s  += v.x + v.y + v.z + v.w;
            ss += v.x * v.x + v.y * v.y + v.z * v.z + v.w * v.w;
        }
    }
    __shared__ float rs[256], rss[256];
    rs[t] = s; rss[t] = ss;
    __syncthreads();
    for (int o = 128; o > 0; o >>= 1) {
        if (t < o) { rs[t] += rs[t + o]; rss[t] += rss[t + o]; }
        __syncthreads();
    }
    if (t == 0) {
        const float inv = 1.f / (float)(BATCH * NPOS);
        float mean = rs[0] * inv;
        float var  = rss[0] * inv - mean * mean;
        g_mean[c] = mean;
        g_rstd[c] = rsqrtf(var + 1e-5f);
    }
}

// =================================================================
// K4: z = (wy - mean)*rstd*gamma + beta + x
// =================================================================
__global__ __launch_bounds__(256) void final_kernel(
    const float* __restrict__ x,
    const float* __restrict__ gamma, const float* __restrict__ beta,
    float* __restrict__ z)
{
    size_t i4 = (size_t)blockIdx.x * 256 + threadIdx.x;
    size_t i  = i4 * 4;
    int c = (int)((i >> 12) & 255);
    float m = g_mean[c], r = g_rstd[c], ga = gamma[c], be = beta[c];
    float4 wy = *(const float4*)&g_WY[i];
    float4 xv = *(const float4*)&x[i];
    float4 o;
    o.x = (wy.x - m) * r * ga + be + xv.x;
    o.y = (wy.y - m) * r * ga + be + xv.y;
    o.z = (wy.z - m) * r * ga + be + xv.z;
    o.w = (wy.w - m) * r * ga + be + xv.w;
    *(float4*)&z[i] = o;
}

// =================================================================
extern "C" void kernel_launch(void* const* d_in, const int* in_sizes, int n_in,
                              void* d_out, int out_size)
{
    const float* x       = (const float*)d_in[0];
    const float* g_w     = (const float*)d_in[1];
    const float* g_b     = (const float*)d_in[2];
    const float* theta_w = (const float*)d_in[3];
    const float* theta_b = (const float*)d_in[4];
    const float* phi_w   = (const float*)d_in[5];
    const float* phi_b   = (const float*)d_in[6];
    const float* W_w     = (const float*)d_in[7];
    const float* W_b     = (const float*)d_in[8];
    const float* bn_g    = (const float*)d_in[9];
    const float* bn_b    = (const float*)d_in[10];
    float* z = (float*)d_out;

    cudaFuncSetAttribute(attn_kernel, cudaFuncAttributeMaxDynamicSharedMemorySize,
                         SMEM_F * (int)sizeof(float));

    proj_kernel<<<dim3(32, 6, 8), 256>>>(x, g_w, g_b, theta_w, theta_b, phi_w, phi_b);
    attn_kernel<<<dim3(64, 8), 256, SMEM_F * sizeof(float)>>>(W_w, W_b);
    stats_kernel<<<256, 256>>>();
    final_kernel<<<8192, 256>>>(x, bn_g, bn_b, z);
}

// round 5
// speedup vs baseline: 2.3301x; 2.3301x over previous
#include <cuda_runtime.h>
#include <cuda_bf16.h>
#include <math.h>
#include <stdint.h>

#define BATCH 8
#define CIN   256
#define CI    128
#define NPOS  4096

// ---------------- scratch (allocation-free: __device__ globals) ----------------
// bf16 2-way splits. TH/PH position-major [b][n][c]; G chan-major [b][c][n].
__device__ __align__(16) __nv_bfloat16 g_THh[(size_t)BATCH * NPOS * CI];
__device__ __align__(16) __nv_bfloat16 g_THl[(size_t)BATCH * NPOS * CI];
__device__ __align__(16) __nv_bfloat16 g_PHh[(size_t)BATCH * NPOS * CI];
__device__ __align__(16) __nv_bfloat16 g_PHl[(size_t)BATCH * NPOS * CI];
__device__ __align__(16) __nv_bfloat16 g_Gh [(size_t)BATCH * CI * NPOS];
__device__ __align__(16) __nv_bfloat16 g_Gl [(size_t)BATCH * CI * NPOS];
__device__ __align__(16) __nv_bfloat16 g_Wh [CIN * CI];
__device__ __align__(16) __nv_bfloat16 g_Wl [CIN * CI];
__device__ float g_WY[(size_t)BATCH * CIN * NPOS];   // W(y) [b][o][n]
__device__ float g_mean[CIN];
__device__ float g_rstd[CIN];

// ---------------- helpers ----------------
__device__ __forceinline__ uint32_t s2u(const void* p) {
    uint32_t a;
    asm("{ .reg .u64 t; cvta.to.shared.u64 t, %1; cvt.u32.u64 %0, t; }" : "=r"(a) : "l"(p));
    return a;
}
__device__ __forceinline__ void ldsm4(uint32_t r[4], uint32_t addr) {
    asm volatile("ldmatrix.sync.aligned.m8n8.x4.shared.b16 {%0,%1,%2,%3}, [%4];"
                 : "=r"(r[0]), "=r"(r[1]), "=r"(r[2]), "=r"(r[3]) : "r"(addr));
}
__device__ __forceinline__ void mma16816(float d[4], const uint32_t a[4],
                                         uint32_t b0, uint32_t b1) {
    asm volatile(
        "mma.sync.aligned.m16n8k16.row.col.f32.bf16.bf16.f32 "
        "{%0,%1,%2,%3}, {%4,%5,%6,%7}, {%8,%9}, {%0,%1,%2,%3};"
        : "+f"(d[0]), "+f"(d[1]), "+f"(d[2]), "+f"(d[3])
        : "r"(a[0]), "r"(a[1]), "r"(a[2]), "r"(a[3]), "r"(b0), "r"(b1));
}
__device__ __forceinline__ uint32_t pkbf(float a, float b, float* ra, float* rb) {
    __nv_bfloat16 ha = __float2bfloat16(a);
    __nv_bfloat16 hb = __float2bfloat16(b);
    *ra = a - __bfloat162float(ha);
    *rb = b - __bfloat162float(hb);
    return (uint32_t)__bfloat16_as_ushort(ha) | ((uint32_t)__bfloat16_as_ushort(hb) << 16);
}
__device__ __forceinline__ uint32_t pkbf2(float a, float b) {
    return (uint32_t)__bfloat16_as_ushort(__float2bfloat16(a)) |
           ((uint32_t)__bfloat16_as_ushort(__float2bfloat16(b)) << 16);
}

// =================================================================
// K0: split W_w into bf16 hi/lo
// =================================================================
__global__ __launch_bounds__(256) void split_w_kernel(const float* __restrict__ W_w)
{
    int i = blockIdx.x * 256 + threadIdx.x;   // 32768 total
    float v = W_w[i];
    __nv_bfloat16 h = __float2bfloat16(v);
    g_Wh[i] = h;
    g_Wl[i] = __float2bfloat16(v - __bfloat162float(h));
}

// =================================================================
// K1: projections (fp32 compute) -> bf16 hi/lo splits.
// theta/phi written position-major [b][n][c]; g chan-major [b][c][n].
// =================================================================
__global__ __launch_bounds__(256) void proj_kernel(
    const float* __restrict__ x,
    const float* __restrict__ g_w,  const float* __restrict__ g_b,
    const float* __restrict__ th_w, const float* __restrict__ th_b,
    const float* __restrict__ ph_w, const float* __restrict__ ph_b)
{
    __shared__ float As[16][68];
    __shared__ float Bs[16][128];

    const int t    = threadIdx.x;
    const int b    = blockIdx.z;
    const int oblk = blockIdx.y;
    const int n0   = blockIdx.x * 128;
    const int which = oblk >> 1;
    const int o0    = (oblk & 1) * 64;

    const float* wsrc; const float* bsrc;
    if (which == 0)      { wsrc = th_w; bsrc = th_b; }
    else if (which == 1) { wsrc = ph_w; bsrc = ph_b; }
    else                 { wsrc = g_w;  bsrc = g_b;  }

    const int u = t & 15;
    const int v = t >> 4;
    const float* xb = x + (size_t)b * CIN * NPOS;

    float acc[4][8];
    #pragma unroll
    for (int i = 0; i < 4; i++)
        #pragma unroll
        for (int j = 0; j < 8; j++) acc[i][j] = 0.f;

    for (int k0 = 0; k0 < CIN; k0 += 16) {
        __syncthreads();
        {
            int o  = t >> 2;
            int cg = (t & 3) * 4;
            float4 w4 = *(const float4*)&wsrc[(size_t)(o0 + o) * CIN + k0 + cg];
            As[cg + 0][o] = w4.x; As[cg + 1][o] = w4.y;
            As[cg + 2][o] = w4.z; As[cg + 3][o] = w4.w;
        }
        #pragma unroll
        for (int i = 0; i < 2; i++) {
            int fidx = i * 256 + t;
            int r    = fidx >> 5;
            int c4   = (fidx & 31) * 4;
            *(float4*)&Bs[r][c4] = *(const float4*)&xb[(size_t)(k0 + r) * NPOS + n0 + c4];
        }
        __syncthreads();
        #pragma unroll
        for (int k = 0; k < 16; k++) {
            float4 a  = *(const float4*)&As[k][4 * u];
            float4 b0 = *(const float4*)&Bs[k][8 * v];
            float4 b1 = *(const float4*)&Bs[k][8 * v + 4];
            float av[4] = {a.x, a.y, a.z, a.w};
            float bv[8] = {b0.x, b0.y, b0.z, b0.w, b1.x, b1.y, b1.z, b1.w};
            #pragma unroll
            for (int i = 0; i < 4; i++)
                #pragma unroll
                for (int j = 0; j < 8; j++) acc[i][j] += av[i] * bv[j];
        }
    }

    float bias[4];
    #pragma unroll
    for (int i = 0; i < 4; i++) bias[i] = bsrc[o0 + 4 * u + i];

    if (which <= 1) {
        __nv_bfloat16* dh = (which == 0) ? g_THh : g_PHh;
        __nv_bfloat16* dl = (which == 0) ? g_THl : g_PHl;
        #pragma unroll
        for (int j = 0; j < 8; j++) {
            int n = n0 + 8 * v + j;
            float r0, r1, r2, r3;
            uint32_t h01 = pkbf(acc[0][j] + bias[0], acc[1][j] + bias[1], &r0, &r1);
            uint32_t h23 = pkbf(acc[2][j] + bias[2], acc[3][j] + bias[3], &r2, &r3);
            uint32_t l01 = pkbf2(r0, r1);
            uint32_t l23 = pkbf2(r2, r3);
            size_t base = ((size_t)b * NPOS + n) * CI + o0 + 4 * u;
            *(uint2*)&dh[base] = make_uint2(h01, h23);
            *(uint2*)&dl[base] = make_uint2(l01, l23);
        }
    } else {
        #pragma unroll
        for (int i = 0; i < 4; i++) {
            int c = o0 + 4 * u + i;
            float rr[8];
            uint32_t h[4], l[4];
            #pragma unroll
            for (int jp = 0; jp < 4; jp++)
                h[jp] = pkbf(acc[i][2 * jp] + bias[i], acc[i][2 * jp + 1] + bias[i],
                             &rr[2 * jp], &rr[2 * jp + 1]);
            #pragma unroll
            for (int jp = 0; jp < 4; jp++) l[jp] = pkbf2(rr[2 * jp], rr[2 * jp + 1]);
            size_t base = ((size_t)b * CI + c) * NPOS + n0 + 8 * v;
            *(uint4*)&g_Gh[base] = make_uint4(h[0], h[1], h[2], h[3]);
            *(uint4*)&g_Gl[base] = make_uint4(l[0], l[1], l[2], l[3]);
        }
    }
}

// =================================================================
// K2: HMMA (mma.sync bf16 split) attention + fused W-conv epilogue.
// CTA: 128 queries x one batch. 8 warps; warp w owns query rows [16w,16w+16).
// Unnormalized exp (logits < ~30), fp32 row-sums, normalize at end.
// =================================================================
#define SQ 272   // 136 bf16 row stride (Q/K/Y/W tiles)
#define SP 144   // 72 bf16 row stride (P/G tiles)
#define SM_QH 0
#define SM_QL 34816
#define SM_KH 69632
#define SM_KL 87040
#define SM_GH 104448
#define SM_GL 122880
#define SM_PH 141312
#define SM_PL 159744
#define SMEM_BYTES 178176
// epilogue aliases
#define SM_YH 0
#define SM_YL 34816
#define SM_WH 69632
#define SM_WL 104448

__global__ __launch_bounds__(256, 1) void attn_mma_kernel(const float* __restrict__ W_b)
{
    extern __shared__ __align__(16) char smem[];
    const uint32_t sb = s2u(smem);
    const int t = threadIdx.x, w = t >> 5, L = t & 31;
    const int b = blockIdx.y;
    const int q0 = blockIdx.x * 128;
    const int g  = L >> 2, tc = L & 3;

    // ---- load resident Q tiles (both splits) ----
    {
        const __nv_bfloat16* qh = g_THh + ((size_t)b * NPOS + q0) * CI;
        const __nv_bfloat16* ql = g_THl + ((size_t)b * NPOS + q0) * CI;
        for (int i = t; i < 2048; i += 256) {
            int r = i >> 4, c16 = i & 15;
            uint32_t off = (uint32_t)(r * SQ + c16 * 16);
            *(uint4*)(smem + SM_QH + off) = *(const uint4*)(qh + (size_t)r * CI + c16 * 8);
            *(uint4*)(smem + SM_QL + off) = *(const uint4*)(ql + (size_t)r * CI + c16 * 8);
        }
    }

    // per-lane ldmatrix base addresses
    const int lr = ((L >> 3) & 1) * 8 + (L & 7);   // A-frag row part
    const int lk = (L >> 4) * 16;                  // A-frag k byte offset
    const int bn = (L >> 4) * 8 + (L & 7);         // B-frag row part
    const int bk = ((L >> 3) & 1) * 16;            // B-frag k byte offset

    const uint32_t aQh = sb + SM_QH + (uint32_t)((16 * w + lr) * SQ + lk);
    const uint32_t aQl = aQh + (SM_QL - SM_QH);
    const uint32_t bKh = sb + SM_KH + (uint32_t)(bn * SQ + bk);
    const uint32_t bKl = bKh + (SM_KL - SM_KH);
    const uint32_t bGh = sb + SM_GH + (uint32_t)(bn * SP + bk);
    const uint32_t bGl = bGh + (SM_GL - SM_GH);
    const uint32_t aPh = sb + SM_PH + (uint32_t)((16 * w + lr) * SP + lk);
    const uint32_t aPl = aPh + (SM_PL - SM_PH);

    float yacc[16][4];
    #pragma unroll
    for (int n = 0; n < 16; n++)
        #pragma unroll
        for (int j = 0; j < 4; j++) yacc[n][j] = 0.f;
    float lsum0 = 0.f, lsum1 = 0.f;

    const __nv_bfloat16* khb = g_PHh + (size_t)b * NPOS * CI;
    const __nv_bfloat16* klb = g_PHl + (size_t)b * NPOS * CI;
    const __nv_bfloat16* ghb = g_Gh + (size_t)b * CI * NPOS;
    const __nv_bfloat16* glb = g_Gl + (size_t)b * CI * NPOS;

    for (int mt = 0; mt < NPOS / 64; mt++) {
        const int m0 = mt * 64;
        __syncthreads();   // prev PV done reading K/G
        // ---- K tiles (64 rows x 128 c), both splits ----
        for (int i = t; i < 1024; i += 256) {
            int r = i >> 4, c16 = i & 15;
            uint32_t off = (uint32_t)(r * SQ + c16 * 16);
            const size_t src = (size_t)(m0 + r) * CI + c16 * 8;
            *(uint4*)(smem + SM_KH + off) = *(const uint4*)(khb + src);
            *(uint4*)(smem + SM_KL + off) = *(const uint4*)(klb + src);
        }
        // ---- G tiles (128 c rows x 64 m), both splits ----
        for (int i = t; i < 1024; i += 256) {
            int r = i >> 3, c8 = i & 7;
            uint32_t off = (uint32_t)(r * SP + c8 * 16);
            const size_t src = (size_t)r * NPOS + m0 + c8 * 8;
            *(uint4*)(smem + SM_GH + off) = *(const uint4*)(ghb + src);
            *(uint4*)(smem + SM_GL + off) = *(const uint4*)(glb + src);
        }
        __syncthreads();

        // ---- S = Q.K^T (3 bf16-split GEMMs), warp rows 16w..16w+15, cols 0..63
        float acc[8][4];
        #pragma unroll
        for (int n = 0; n < 8; n++)
            #pragma unroll
            for (int j = 0; j < 4; j++) acc[n][j] = 0.f;

        #pragma unroll 1
        for (int s = 0; s < 3; s++) {
            const uint32_t aB = (s == 2) ? aQl : aQh;
            const uint32_t bB = (s == 1) ? bKl : bKh;
            #pragma unroll
            for (int kk = 0; kk < 8; kk++) {
                uint32_t a[4];
                ldsm4(a, aB + kk * 32);
                #pragma unroll
                for (int np = 0; np < 4; np++) {
                    uint32_t bb[4];
                    ldsm4(bb, bB + np * (16 * SQ) + kk * 32);
                    mma16816(acc[2 * np], a, bb[0], bb[1]);
                    mma16816(acc[2 * np + 1], a, bb[2], bb[3]);
                }
            }
        }

        // ---- softmax: unnormalized exp, row sums, P -> smem (hi/lo) ----
        float s0 = 0.f, s1 = 0.f;
        #pragma unroll
        for (int n = 0; n < 8; n++) {
            float p0 = __expf(acc[n][0]);
            float p1 = __expf(acc[n][1]);
            float p2 = __expf(acc[n][2]);
            float p3 = __expf(acc[n][3]);
            s0 += p0 + p1;
            s1 += p2 + p3;
            float r0, r1;
            uint32_t hp = pkbf(p0, p1, &r0, &r1);
            uint32_t lp = pkbf2(r0, r1);
            uint32_t off = (uint32_t)((16 * w + g) * SP + (8 * n + 2 * tc) * 2);
            *(uint32_t*)(smem + SM_PH + off) = hp;
            *(uint32_t*)(smem + SM_PL + off) = lp;
            hp = pkbf(p2, p3, &r0, &r1);
            lp = pkbf2(r0, r1);
            off += 8 * SP;
            *(uint32_t*)(smem + SM_PH + off) = hp;
            *(uint32_t*)(smem + SM_PL + off) = lp;
        }
        s0 += __shfl_xor_sync(0xffffffffu, s0, 1);
        s0 += __shfl_xor_sync(0xffffffffu, s0, 2);
        s1 += __shfl_xor_sync(0xffffffffu, s1, 1);
        s1 += __shfl_xor_sync(0xffffffffu, s1, 2);
        lsum0 += s0;
        lsum1 += s1;
        __syncthreads();   // all P written

        // ---- PV: yacc += P.G^T (3 splits), cols 0..127 ----
        #pragma unroll 1
        for (int s = 0; s < 3; s++) {
            const uint32_t aB = (s == 2) ? aPl : aPh;
            const uint32_t bB = (s == 1) ? bGl : bGh;
            #pragma unroll
            for (int kk = 0; kk < 4; kk++) {
                uint32_t a[4];
                ldsm4(a, aB + kk * 32);
                #pragma unroll
                for (int np = 0; np < 8; np++) {
                    uint32_t bb[4];
                    ldsm4(bb, bB + np * (16 * SP) + kk * 32);
                    mma16816(yacc[2 * np], a, bb[0], bb[1]);
                    mma16816(yacc[2 * np + 1], a, bb[2], bb[3]);
                }
            }
        }
    }

    // ---- normalize, split Y into smem (aliases Q region) ----
    {
        float rv0 = 1.f / lsum0, rv1 = 1.f / lsum1;
        #pragma unroll
        for (int n = 0; n < 16; n++) {
            float y0 = yacc[n][0] * rv0, y1 = yacc[n][1] * rv0;
            float y2 = yacc[n][2] * rv1, y3 = yacc[n][3] * rv1;
            float r0, r1;
            uint32_t hp = pkbf(y0, y1, &r0, &r1);
            uint32_t lp = pkbf2(r0, r1);
            uint32_t off = (uint32_t)((16 * w + g) * SQ + (8 * n + 2 * tc) * 2);
            *(uint32_t*)(smem + SM_YH + off) = hp;
            *(uint32_t*)(smem + SM_YL + off) = lp;
            hp = pkbf(y2, y3, &r0, &r1);
            lp = pkbf2(r0, r1);
            off += 8 * SQ;
            *(uint32_t*)(smem + SM_YH + off) = hp;
            *(uint32_t*)(smem + SM_YL + off) = lp;
        }
    }

    // ---- WY = W_w @ Y + W_b, two 128-channel halves ----
    const uint32_t aYh = sb + SM_YH + (uint32_t)((16 * w + lr) * SQ + lk);
    const uint32_t aYl = aYh + (SM_YL - SM_YH);
    const uint32_t bWh = sb + SM_WH + (uint32_t)(bn * SQ + bk);
    const uint32_t bWl = bWh + (SM_WL - SM_WH);
    float* WYb = g_WY + (size_t)b * CIN * NPOS + q0;

    #pragma unroll 1
    for (int h = 0; h < 2; h++) {
        __syncthreads();   // Y visible; prev reads of Wt/K/G done
        const __nv_bfloat16* wh = g_Wh + (size_t)h * 128 * CI;
        const __nv_bfloat16* wl = g_Wl + (size_t)h * 128 * CI;
        for (int i = t; i < 2048; i += 256) {
            int r = i >> 4, c16 = i & 15;
            uint32_t off = (uint32_t)(r * SQ + c16 * 16);
            *(uint4*)(smem + SM_WH + off) = *(const uint4*)(wh + (size_t)r * CI + c16 * 8);
            *(uint4*)(smem + SM_WL + off) = *(const uint4*)(wl + (size_t)r * CI + c16 * 8);
        }
        __syncthreads();

        float wacc[16][4];
        #pragma unroll
        for (int n = 0; n < 16; n++)
            #pragma unroll
            for (int j = 0; j < 4; j++) wacc[n][j] = 0.f;

        #pragma unroll 1
        for (int s = 0; s < 3; s++) {
            const uint32_t aB = (s == 2) ? aYl : aYh;
            const uint32_t bB = (s == 1) ? bWl : bWh;
            #pragma unroll
            for (int kk = 0; kk < 8; kk++) {
                uint32_t a[4];
                ldsm4(a, aB + kk * 32);
                #pragma unroll
                for (int np = 0; np < 8; np++) {
                    uint32_t bb[4];
                    ldsm4(bb, bB + np * (16 * SQ) + kk * 32);
                    mma16816(wacc[2 * np], a, bb[0], bb[1]);
                    mma16816(wacc[2 * np + 1], a, bb[2], bb[3]);
                }
            }
        }

        #pragma unroll
        for (int n = 0; n < 16; n++) {
            int o = h * 128 + 8 * n + 2 * tc;
            float b0 = __ldg(&W_b[o]);
            float b1 = __ldg(&W_b[o + 1]);
            int r0 = 16 * w + g;
            WYb[(size_t)o * NPOS + r0]           = wacc[n][0] + b0;
            WYb[(size_t)(o + 1) * NPOS + r0]     = wacc[n][1] + b1;
            WYb[(size_t)o * NPOS + r0 + 8]       = wacc[n][2] + b0;
            WYb[(size_t)(o + 1) * NPOS + r0 + 8] = wacc[n][3] + b1;
        }
    }
}

// =================================================================
// K3: per-channel BN statistics over (B, N)
// =================================================================
__global__ __launch_bounds__(256) void stats_kernel()
{
    const int c = blockIdx.x;
    const int t = threadIdx.x;
    float s = 0.f, ss = 0.f;
    for (int b = 0; b < BATCH; b++) {
        const float* p = g_WY + ((size_t)b * CIN + c) * NPOS;
        for (int i = t; i < NPOS / 4; i += 256) {
            float4 v = *(const float4*)&p[4 * i];
            s  += v.x + v.y + v.z + v.w;
            ss += v.x * v.x + v.y * v.y + v.z * v.z + v.w * v.w;
        }
    }
    __shared__ float rs[256], rss[256];
    rs[t] = s; rss[t] = ss;
    __syncthreads();
    for (int o = 128; o > 0; o >>= 1) {
        if (t < o) { rs[t] += rs[t + o]; rss[t] += rss[t + o]; }
        __syncthreads();
    }
    if (t == 0) {
        const float inv = 1.f / (float)(BATCH * NPOS);
        float mean = rs[0] * inv;
        float var  = rss[0] * inv - mean * mean;
        g_mean[c] = mean;
        g_rstd[c] = rsqrtf(var + 1e-5f);
    }
}

// =================================================================
// K4: z = (wy - mean)*rstd*gamma + beta + x
// =================================================================
__global__ __launch_bounds__(256) void final_kernel(
    const float* __restrict__ x,
    const float* __restrict__ gamma, const float* __restrict__ beta,
    float* __restrict__ z)
{
    size_t i4 = (size_t)blockIdx.x * 256 + threadIdx.x;
    size_t i  = i4 * 4;
    int c = (int)((i >> 12) & 255);
    float m = g_mean[c], r = g_rstd[c], ga = gamma[c], be = beta[c];
    float4 wy = *(const float4*)&g_WY[i];
    float4 xv = *(const float4*)&x[i];
    float4 o;
    o.x = (wy.x - m) * r * ga + be + xv.x;
    o.y = (wy.y - m) * r * ga + be + xv.y;
    o.z = (wy.z - m) * r * ga + be + xv.z;
    o.w = (wy.w - m) * r * ga + be + xv.w;
    *(float4*)&z[i] = o;
}

// =================================================================
extern "C" void kernel_launch(void* const* d_in, const int* in_sizes, int n_in,
                              void* d_out, int out_size)
{
    const float* x       = (const float*)d_in[0];
    const float* g_w     = (const float*)d_in[1];
    const float* g_b     = (const float*)d_in[2];
    const float* theta_w = (const float*)d_in[3];
    const float* theta_b = (const float*)d_in[4];
    const float* phi_w   = (const float*)d_in[5];
    const float* phi_b   = (const float*)d_in[6];
    const float* W_w     = (const float*)d_in[7];
    const float* W_b     = (const float*)d_in[8];
    const float* bn_g    = (const float*)d_in[9];
    const float* bn_b    = (const float*)d_in[10];
    float* z = (float*)d_out;

    cudaFuncSetAttribute(attn_mma_kernel, cudaFuncAttributeMaxDynamicSharedMemorySize,
                         SMEM_BYTES);

    split_w_kernel<<<128, 256>>>(W_w);
    proj_kernel<<<dim3(32, 6, 8), 256>>>(x, g_w, g_b, theta_w, theta_b, phi_w, phi_b);
    attn_mma_kernel<<<dim3(32, 8), 256, SMEM_BYTES>>>(W_b);
    stats_kernel<<<256, 256>>>();
    final_kernel<<<8192, 256>>>(x, bn_g, bn_b, z);
}

// round 6
// speedup vs baseline: 3.6708x; 1.5754x over previous
#include <cuda_runtime.h>
#include <cuda_bf16.h>
#include <math.h>
#include <stdint.h>

#define BATCH 8
#define CIN   256
#define CI    128
#define NPOS  4096

// ---------------- scratch (allocation-free: __device__ globals) ----------------
__device__ __align__(16) __nv_bfloat16 g_Xh [(size_t)BATCH * CIN * NPOS];  // x hi [b][c][n]
__device__ __align__(16) __nv_bfloat16 g_Xl [(size_t)BATCH * CIN * NPOS];
__device__ __align__(16) __nv_bfloat16 g_THh[(size_t)BATCH * NPOS * CI];   // theta [b][n][c]
__device__ __align__(16) __nv_bfloat16 g_THl[(size_t)BATCH * NPOS * CI];
__device__ __align__(16) __nv_bfloat16 g_PHh[(size_t)BATCH * NPOS * CI];   // phi   [b][n][c]
__device__ __align__(16) __nv_bfloat16 g_PHl[(size_t)BATCH * NPOS * CI];
__device__ __align__(16) __nv_bfloat16 g_Gh [(size_t)BATCH * CI * NPOS];   // g     [b][c][n]
__device__ __align__(16) __nv_bfloat16 g_Gl [(size_t)BATCH * CI * NPOS];
__device__ __align__(16) __nv_bfloat16 g_WQh[2 * CI * CIN];   // [theta_w ; phi_w] [256][256]
__device__ __align__(16) __nv_bfloat16 g_WQl[2 * CI * CIN];
__device__ __align__(16) __nv_bfloat16 g_WGh[CI * CIN];       // g_w [128][256]
__device__ __align__(16) __nv_bfloat16 g_WGl[CI * CIN];
__device__ __align__(16) __nv_bfloat16 g_Wh [CIN * CI];       // W_w [256][128]
__device__ __align__(16) __nv_bfloat16 g_Wl [CIN * CI];
__device__ float g_WY[(size_t)BATCH * CIN * NPOS];            // W(y) [b][o][n]
__device__ float g_ps[4 * CIN], g_pss[4 * CIN];
__device__ float g_mean[CIN];
__device__ float g_rstd[CIN];

// ---------------- helpers ----------------
__device__ __forceinline__ uint32_t s2u(const void* p) {
    uint32_t a;
    asm("{ .reg .u64 t; cvta.to.shared.u64 t, %1; cvt.u32.u64 %0, t; }" : "=r"(a) : "l"(p));
    return a;
}
__device__ __forceinline__ void ldsm4(uint32_t r[4], uint32_t addr) {
    asm volatile("ldmatrix.sync.aligned.m8n8.x4.shared.b16 {%0,%1,%2,%3}, [%4];"
                 : "=r"(r[0]), "=r"(r[1]), "=r"(r[2]), "=r"(r[3]) : "r"(addr));
}
__device__ __forceinline__ void ldsm4t(uint32_t r[4], uint32_t addr) {
    asm volatile("ldmatrix.sync.aligned.m8n8.x4.trans.shared.b16 {%0,%1,%2,%3}, [%4];"
                 : "=r"(r[0]), "=r"(r[1]), "=r"(r[2]), "=r"(r[3]) : "r"(addr));
}
__device__ __forceinline__ void mma16816(float d[4], const uint32_t a[4],
                                         uint32_t b0, uint32_t b1) {
    asm volatile(
        "mma.sync.aligned.m16n8k16.row.col.f32.bf16.bf16.f32 "
        "{%0,%1,%2,%3}, {%4,%5,%6,%7}, {%8,%9}, {%0,%1,%2,%3};"
        : "+f"(d[0]), "+f"(d[1]), "+f"(d[2]), "+f"(d[3])
        : "r"(a[0]), "r"(a[1]), "r"(a[2]), "r"(a[3]), "r"(b0), "r"(b1));
}
__device__ __forceinline__ void cpa16(uint32_t dst, const void* src) {
    asm volatile("cp.async.cg.shared.global [%0], [%1], 16;" :: "r"(dst), "l"(src));
}
#define CP_COMMIT() asm volatile("cp.async.commit_group;" ::: "memory")
#define CP_WAIT0()  asm volatile("cp.async.wait_group 0;" ::: "memory")
#define CP_WAIT1()  asm volatile("cp.async.wait_group 1;" ::: "memory")

__device__ __forceinline__ uint32_t pkbf(float a, float b, float* ra, float* rb) {
    __nv_bfloat16 ha = __float2bfloat16(a);
    __nv_bfloat16 hb = __float2bfloat16(b);
    *ra = a - __bfloat162float(ha);
    *rb = b - __bfloat162float(hb);
    return (uint32_t)__bfloat16_as_ushort(ha) | ((uint32_t)__bfloat16_as_ushort(hb) << 16);
}
__device__ __forceinline__ uint32_t pkbf2(float a, float b) {
    return (uint32_t)__bfloat16_as_ushort(__float2bfloat16(a)) |
           ((uint32_t)__bfloat16_as_ushort(__float2bfloat16(b)) << 16);
}

// =================================================================
// K0a: split x -> bf16 hi/lo
// =================================================================
__global__ __launch_bounds__(256) void split_x_kernel(const float* __restrict__ x)
{
    size_t i = ((size_t)blockIdx.x * 256 + threadIdx.x) * 4;
    float4 v = *(const float4*)&x[i];
    float r0, r1, r2, r3;
    uint32_t h01 = pkbf(v.x, v.y, &r0, &r1);
    uint32_t h23 = pkbf(v.z, v.w, &r2, &r3);
    *(uint2*)&g_Xh[i] = make_uint2(h01, h23);
    *(uint2*)&g_Xl[i] = make_uint2(pkbf2(r0, r1), pkbf2(r2, r3));
}

// =================================================================
// K0b: split all weights -> bf16 hi/lo
// =================================================================
__global__ __launch_bounds__(256) void split_wts_kernel(
    const float* __restrict__ thw, const float* __restrict__ phw,
    const float* __restrict__ gw,  const float* __restrict__ Ww)
{
    int i = blockIdx.x * 256 + threadIdx.x;   // 0..131071
    int which = i >> 15, j = i & 32767;
    float v;
    __nv_bfloat16 *dh, *dl;
    int o;
    if (which == 0)      { v = thw[j]; dh = g_WQh; dl = g_WQl; o = j; }
    else if (which == 1) { v = phw[j]; dh = g_WQh; dl = g_WQl; o = 32768 + j; }
    else if (which == 2) { v = gw[j];  dh = g_WGh; dl = g_WGl; o = j; }
    else                 { v = Ww[j];  dh = g_Wh;  dl = g_Wl;  o = j; }
    __nv_bfloat16 h = __float2bfloat16(v);
    dh[o] = h;
    dl[o] = __float2bfloat16(v - __bfloat162float(h));
}

// =================================================================
// K1a: theta/phi projection (HMMA). out[n][o] = sum_c x[c][n]*w[o][c] + b[o]
// A = x^T (trans ldmatrix), B = w. Output position-major [b][n][c] splits.
// CTA: 128 n x 256 o (theta|phi), K=256 in 8 chunks of 32, double-buffered.
// =================================================================
#define PSQ 272   // xs row stride (128 n * 2B + 16)
#define PSW 80    // ws row stride (32 c * 2B + 16)
#define PJ_XH 0
#define PJ_XL 8704
#define PJ_WH 17408
#define PJ_WL 37888
#define PJ_BUF 58368
#define PJ_BIAS 116736
#define PJ_SMEM 117760

__global__ __launch_bounds__(256, 1) void proj_npos_kernel(
    const float* __restrict__ th_b, const float* __restrict__ ph_b)
{
    extern __shared__ __align__(16) char smem[];
    const uint32_t sb = s2u(smem);
    const int t = threadIdx.x, w = t >> 5, L = t & 31;
    const int g = L >> 2, tc = L & 3;
    const int b = blockIdx.y;
    const int n0 = blockIdx.x * 128;

    float* bias = (float*)(smem + PJ_BIAS);
    bias[t] = (t < 128) ? th_b[t] : ph_b[t - 128];

    const __nv_bfloat16* xh = g_Xh + (size_t)b * CIN * NPOS + n0;
    const __nv_bfloat16* xl = g_Xl + (size_t)b * CIN * NPOS + n0;

    // lane offsets
    const uint32_t aoff = (uint32_t)(((L & 7) + ((L >> 4) & 1) * 8) * PSQ + 32 * w +
                                     ((L >> 3) & 1) * 16);
    const uint32_t boff = (uint32_t)(((L >> 4) * 8 + (L & 7)) * PSW + ((L >> 3) & 1) * 16);

    float acc[32][4];
    #pragma unroll
    for (int j = 0; j < 32; j++)
        #pragma unroll
        for (int k = 0; k < 4; k++) acc[j][k] = 0.f;

    // issue chunk 0
    {
        uint32_t base = sb;
        for (int i = t; i < 512; i += 256) {
            int r = i >> 4, c16 = i & 15;
            uint32_t doff = (uint32_t)(r * PSQ + c16 * 16);
            cpa16(base + PJ_XH + doff, xh + (size_t)r * NPOS + c16 * 8);
            cpa16(base + PJ_XL + doff, xl + (size_t)r * NPOS + c16 * 8);
        }
        for (int i = t; i < 1024; i += 256) {
            int r = i >> 2, c4 = i & 3;
            uint32_t doff = (uint32_t)(r * PSW + c4 * 16);
            cpa16(base + PJ_WH + doff, g_WQh + (size_t)r * CIN + c4 * 8);
            cpa16(base + PJ_WL + doff, g_WQl + (size_t)r * CIN + c4 * 8);
        }
        CP_COMMIT();
    }

    #pragma unroll 1
    for (int ch = 0; ch < 8; ch++) {
        if (ch < 7) {
            int c0 = (ch + 1) * 32;
            uint32_t base = sb + ((ch + 1) & 1) * PJ_BUF;
            for (int i = t; i < 512; i += 256) {
                int r = i >> 4, c16 = i & 15;
                uint32_t doff = (uint32_t)(r * PSQ + c16 * 16);
                cpa16(base + PJ_XH + doff, xh + (size_t)(c0 + r) * NPOS + c16 * 8);
                cpa16(base + PJ_XL + doff, xl + (size_t)(c0 + r) * NPOS + c16 * 8);
            }
            for (int i = t; i < 1024; i += 256) {
                int r = i >> 2, c4 = i & 3;
                uint32_t doff = (uint32_t)(r * PSW + c4 * 16);
                cpa16(base + PJ_WH + doff, g_WQh + (size_t)r * CIN + c0 + c4 * 8);
                cpa16(base + PJ_WL + doff, g_WQl + (size_t)r * CIN + c0 + c4 * 8);
            }
            CP_COMMIT();
            CP_WAIT1();
        } else {
            CP_WAIT0();
        }
        __syncthreads();
        const uint32_t xbase = sb + (ch & 1) * PJ_BUF;
        const uint32_t aB = xbase + PJ_XH + aoff;
        const uint32_t bB = xbase + PJ_WH + boff;
        #pragma unroll
        for (int kk = 0; kk < 2; kk++) {
            uint32_t ah[4], al[4];
            ldsm4t(ah, aB + kk * 16 * PSQ);
            ldsm4t(al, aB + 8704 + kk * 16 * PSQ);
            #pragma unroll
            for (int np = 0; np < 16; np++) {
                uint32_t bh[4], bl[4];
                ldsm4(bh, bB + np * (16 * PSW) + kk * 32);
                ldsm4(bl, bB + 20480 + np * (16 * PSW) + kk * 32);
                mma16816(acc[2 * np],     ah, bh[0], bh[1]);
                mma16816(acc[2 * np + 1], ah, bh[2], bh[3]);
                mma16816(acc[2 * np],     ah, bl[0], bl[1]);
                mma16816(acc[2 * np + 1], ah, bl[2], bl[3]);
                mma16816(acc[2 * np],     al, bh[0], bh[1]);
                mma16816(acc[2 * np + 1], al, bh[2], bh[3]);
            }
        }
        __syncthreads();
    }

    // epilogue: write [n][c] splits
    const int nrow = n0 + 16 * w + g;
    const size_t rb0 = ((size_t)b * NPOS + nrow) * CI;
    const size_t rb1 = rb0 + (size_t)8 * CI;
    #pragma unroll
    for (int j = 0; j < 32; j++) {
        int o = 8 * j + 2 * tc;
        float b0 = bias[o], b1 = bias[o + 1];
        __nv_bfloat16 *dh, *dl;
        int c;
        if (o < 128) { dh = g_THh; dl = g_THl; c = o; }
        else         { dh = g_PHh; dl = g_PHl; c = o - 128; }
        float r0, r1;
        uint32_t hp = pkbf(acc[j][0] + b0, acc[j][1] + b1, &r0, &r1);
        uint32_t lp = pkbf2(r0, r1);
        *(uint32_t*)(dh + rb0 + c) = hp;
        *(uint32_t*)(dl + rb0 + c) = lp;
        hp = pkbf(acc[j][2] + b0, acc[j][3] + b1, &r0, &r1);
        lp = pkbf2(r0, r1);
        *(uint32_t*)(dh + rb1 + c) = hp;
        *(uint32_t*)(dl + rb1 + c) = lp;
    }
}

// =================================================================
// K1b: g projection (HMMA). out[o][n] = sum_c w[o][c]*x[c][n] + b[o]
// A = w (standard), B = x^T (trans). Output chan-major [b][c][n] splits.
// CTA: 128 o x 128 n, K=256 in 8 chunks of 32, double-buffered.
// =================================================================
#define PG_XH 0
#define PG_XL 8704
#define PG_WH 17408
#define PG_WL 27648
#define PG_BUF 37888
#define PG_BIAS 75776
#define PG_SMEM 76800

__global__ __launch_bounds__(256, 1) void proj_chan_kernel(const float* __restrict__ g_b)
{
    extern __shared__ __align__(16) char smem[];
    const uint32_t sb = s2u(smem);
    const int t = threadIdx.x, w = t >> 5, L = t & 31;
    const int g = L >> 2, tc = L & 3;
    const int b = blockIdx.y;
    const int n0 = blockIdx.x * 128;

    float* bias = (float*)(smem + PG_BIAS);
    if (t < 128) bias[t] = g_b[t];

    const __nv_bfloat16* xh = g_Xh + (size_t)b * CIN * NPOS + n0;
    const __nv_bfloat16* xl = g_Xl + (size_t)b * CIN * NPOS + n0;

    const uint32_t aoff = (uint32_t)((16 * w + (L & 7) + ((L >> 3) & 1) * 8) * PSW +
                                     (L >> 4) * 16);
    const uint32_t boff = (uint32_t)(((L & 7) + ((L >> 3) & 1) * 8) * PSQ + (L >> 4) * 16);

    float acc[16][4];
    #pragma unroll
    for (int j = 0; j < 16; j++)
        #pragma unroll
        for (int k = 0; k < 4; k++) acc[j][k] = 0.f;

    {
        uint32_t base = sb;
        for (int i = t; i < 512; i += 256) {
            int r = i >> 4, c16 = i & 15;
            uint32_t doff = (uint32_t)(r * PSQ + c16 * 16);
            cpa16(base + PG_XH + doff, xh + (size_t)r * NPOS + c16 * 8);
            cpa16(base + PG_XL + doff, xl + (size_t)r * NPOS + c16 * 8);
        }
        for (int i = t; i < 512; i += 256) {
            int r = i >> 2, c4 = i & 3;
            uint32_t doff = (uint32_t)(r * PSW + c4 * 16);
            cpa16(base + PG_WH + doff, g_WGh + (size_t)r * CIN + c4 * 8);
            cpa16(base + PG_WL + doff, g_WGl + (size_t)r * CIN + c4 * 8);
        }
        CP_COMMIT();
    }

    #pragma unroll 1
    for (int ch = 0; ch < 8; ch++) {
        if (ch < 7) {
            int c0 = (ch + 1) * 32;
            uint32_t base = sb + ((ch + 1) & 1) * PG_BUF;
            for (int i = t; i < 512; i += 256) {
                int r = i >> 4, c16 = i & 15;
                uint32_t doff = (uint32_t)(r * PSQ + c16 * 16);
                cpa16(base + PG_XH + doff, xh + (size_t)(c0 + r) * NPOS + c16 * 8);
                cpa16(base + PG_XL + doff, xl + (size_t)(c0 + r) * NPOS + c16 * 8);
            }
            for (int i = t; i < 512; i += 256) {
                int r = i >> 2, c4 = i & 3;
                uint32_t doff = (uint32_t)(r * PSW + c4 * 16);
                cpa16(base + PG_WH + doff, g_WGh + (size_t)r * CIN + c0 + c4 * 8);
                cpa16(base + PG_WL + doff, g_WGl + (size_t)r * CIN + c0 + c4 * 8);
            }
            CP_COMMIT();
            CP_WAIT1();
        } else {
            CP_WAIT0();
        }
        __syncthreads();
        const uint32_t xbase = sb + (ch & 1) * PG_BUF;
        const uint32_t aB = xbase + PG_WH + aoff;
        const uint32_t bB = xbase + PG_XH + boff;
        #pragma unroll
        for (int kk = 0; kk < 2; kk++) {
            uint32_t ah[4], al[4];
            ldsm4(ah, aB + kk * 32);
            ldsm4(al, aB + 10240 + kk * 32);
            #pragma unroll
            for (int np = 0; np < 8; np++) {
                uint32_t bh[4], bl[4];
                ldsm4t(bh, bB + np * 32 + kk * 16 * PSQ);
                ldsm4t(bl, bB + 8704 + np * 32 + kk * 16 * PSQ);
                mma16816(acc[2 * np],     ah, bh[0], bh[1]);
                mma16816(acc[2 * np + 1], ah, bh[2], bh[3]);
                mma16816(acc[2 * np],     ah, bl[0], bl[1]);
                mma16816(acc[2 * np + 1], ah, bl[2], bl[3]);
                mma16816(acc[2 * np],     al, bh[0], bh[1]);
                mma16816(acc[2 * np + 1], al, bh[2], bh[3]);
            }
        }
        __syncthreads();
    }

    // epilogue: write [c][n] splits
    const int o = 16 * w + g;
    const float b0 = bias[o], b8 = bias[o + 8];
    #pragma unroll
    for (int j = 0; j < 16; j++) {
        int n = 16 * (j >> 1) + 8 * (j & 1) + 2 * tc;
        size_t a0 = ((size_t)b * CI + o) * NPOS + n0 + n;
        size_t a8 = a0 + (size_t)8 * NPOS;
        float r0, r1;
        uint32_t hp = pkbf(acc[j][0] + b0, acc[j][1] + b0, &r0, &r1);
        uint32_t lp = pkbf2(r0, r1);
        *(uint32_t*)(g_Gh + a0) = hp;
        *(uint32_t*)(g_Gl + a0) = lp;
        hp = pkbf(acc[j][2] + b8, acc[j][3] + b8, &r0, &r1);
        lp = pkbf2(r0, r1);
        *(uint32_t*)(g_Gh + a8) = hp;
        *(uint32_t*)(g_Gl + a8) = lp;
    }
}

// =================================================================
// K2: HMMA attention, cp.async pipelined, fused-split loops.
// =================================================================
#define SQ 272
#define SP 144
#define SM_QH  0
#define SM_QL  34816
#define SM_KH  69632
#define SM_KL  87040
#define SM_GH0 104448
#define SM_GL0 122880
#define SM_GH1 141312
#define SM_GL1 159744
#define SM_PH  178176
#define SM_PL  196608
#define SMEM_BYTES 215040
// epilogue aliases
#define SM_YH 0
#define SM_YL 34816
#define SM_WH 69632
#define SM_WL 104448

__global__ __launch_bounds__(256, 1) void attn_mma_kernel(const float* __restrict__ W_b)
{
    extern __shared__ __align__(16) char smem[];
    const uint32_t sb = s2u(smem);
    const int t = threadIdx.x, w = t >> 5, L = t & 31;
    const int b = blockIdx.y;
    const int q0 = blockIdx.x * 128;
    const int g  = L >> 2, tc = L & 3;

    const __nv_bfloat16* qh  = g_THh + ((size_t)b * NPOS + q0) * CI;
    const __nv_bfloat16* ql  = g_THl + ((size_t)b * NPOS + q0) * CI;
    const __nv_bfloat16* khb = g_PHh + (size_t)b * NPOS * CI;
    const __nv_bfloat16* klb = g_PHl + (size_t)b * NPOS * CI;
    const __nv_bfloat16* ghb = g_Gh + (size_t)b * CI * NPOS;
    const __nv_bfloat16* glb = g_Gl + (size_t)b * CI * NPOS;

    // prologue: Q, K(0), G(0 -> buf0) via cp.async
    for (int i = t; i < 2048; i += 256) {
        int r = i >> 4, c16 = i & 15;
        uint32_t doff = (uint32_t)(r * SQ + c16 * 16);
        cpa16(sb + SM_QH + doff, qh + (size_t)r * CI + c16 * 8);
        cpa16(sb + SM_QL + doff, ql + (size_t)r * CI + c16 * 8);
    }
    for (int i = t; i < 1024; i += 256) {
        int r = i >> 4, c16 = i & 15;
        uint32_t doff = (uint32_t)(r * SQ + c16 * 16);
        cpa16(sb + SM_KH + doff, khb + (size_t)r * CI + c16 * 8);
        cpa16(sb + SM_KL + doff, klb + (size_t)r * CI + c16 * 8);
    }
    for (int i = t; i < 1024; i += 256) {
        int r = i >> 3, c8 = i & 7;
        uint32_t doff = (uint32_t)(r * SP + c8 * 16);
        cpa16(sb + SM_GH0 + doff, ghb + (size_t)r * NPOS + c8 * 8);
        cpa16(sb + SM_GL0 + doff, glb + (size_t)r * NPOS + c8 * 8);
    }
    CP_COMMIT();

    // per-lane ldmatrix bases
    const int lr = ((L >> 3) & 1) * 8 + (L & 7);
    const int lk = (L >> 4) * 16;
    const int bn = (L >> 4) * 8 + (L & 7);
    const int bk = ((L >> 3) & 1) * 16;

    const uint32_t aQh = sb + SM_QH + (uint32_t)((16 * w + lr) * SQ + lk);
    const uint32_t aQl = aQh + (SM_QL - SM_QH);
    const uint32_t bKh = sb + SM_KH + (uint32_t)(bn * SQ + bk);
    const uint32_t bKl = bKh + (SM_KL - SM_KH);
    const uint32_t aPh = sb + SM_PH + (uint32_t)((16 * w + lr) * SP + lk);
    const uint32_t aPl = aPh + (SM_PL - SM_PH);
    const uint32_t gOff = (uint32_t)(bn * SP + bk);

    float yacc[16][4];
    #pragma unroll
    for (int n = 0; n < 16; n++)
        #pragma unroll
        for (int j = 0; j < 4; j++) yacc[n][j] = 0.f;
    float lsum0 = 0.f, lsum1 = 0.f;

    #pragma unroll 1
    for (int mt = 0; mt < NPOS / 64; mt++) {
        CP_WAIT0();
        __syncthreads();   // K(mt), G(mt) ready; prev PV done

        // prefetch G(mt+1) into other buffer
        if (mt < 63) {
            const int m1 = mt * 64 + 64;
            const uint32_t gdst = ((mt + 1) & 1) ? SM_GH1 : SM_GH0;
            for (int i = t; i < 1024; i += 256) {
                int r = i >> 3, c8 = i & 7;
                uint32_t doff = gdst + (uint32_t)(r * SP + c8 * 16);
                cpa16(sb + doff, ghb + (size_t)r * NPOS + m1 + c8 * 8);
                cpa16(sb + doff + 18432, glb + (size_t)r * NPOS + m1 + c8 * 8);
            }
            CP_COMMIT();
        }

        // ---- QK fused-split ----
        float acc[8][4];
        #pragma unroll
        for (int n = 0; n < 8; n++)
            #pragma unroll
            for (int j = 0; j < 4; j++) acc[n][j] = 0.f;
        #pragma unroll
        for (int kk = 0; kk < 8; kk++) {
            uint32_t ah[4], al[4];
            ldsm4(ah, aQh + kk * 32);
            ldsm4(al, aQl + kk * 32);
            #pragma unroll
            for (int np = 0; np < 4; np++) {
                uint32_t bh[4], bl[4];
                ldsm4(bh, bKh + np * (16 * SQ) + kk * 32);
                ldsm4(bl, bKl + np * (16 * SQ) + kk * 32);
                mma16816(acc[2 * np],     ah, bh[0], bh[1]);
                mma16816(acc[2 * np + 1], ah, bh[2], bh[3]);
                mma16816(acc[2 * np],     ah, bl[0], bl[1]);
                mma16816(acc[2 * np + 1], ah, bl[2], bl[3]);
                mma16816(acc[2 * np],     al, bh[0], bh[1]);
                mma16816(acc[2 * np + 1], al, bh[2], bh[3]);
            }
        }

        // ---- softmax: unnormalized exp, row sums, P -> smem (hi/lo) ----
        float s0 = 0.f, s1 = 0.f;
        #pragma unroll
        for (int n = 0; n < 8; n++) {
            float p0 = __expf(acc[n][0]);
            float p1 = __expf(acc[n][1]);
            float p2 = __expf(acc[n][2]);
            float p3 = __expf(acc[n][3]);
            s0 += p0 + p1;
            s1 += p2 + p3;
            float r0, r1;
            uint32_t hp = pkbf(p0, p1, &r0, &r1);
            uint32_t lp = pkbf2(r0, r1);
            uint32_t off = (uint32_t)((16 * w + g) * SP + (8 * n + 2 * tc) * 2);
            *(uint32_t*)(smem + SM_PH + off) = hp;
            *(uint32_t*)(smem + SM_PL + off) = lp;
            hp = pkbf(p2, p3, &r0, &r1);
            lp = pkbf2(r0, r1);
            off += 8 * SP;
            *(uint32_t*)(smem + SM_PH + off) = hp;
            *(uint32_t*)(smem + SM_PL + off) = lp;
        }
        s0 += __shfl_xor_sync(0xffffffffu, s0, 1);
        s0 += __shfl_xor_sync(0xffffffffu, s0, 2);
        s1 += __shfl_xor_sync(0xffffffffu, s1, 1);
        s1 += __shfl_xor_sync(0xffffffffu, s1, 2);
        lsum0 += s0;
        lsum1 += s1;
        __syncthreads();   // P visible; all QK reads of K done

        // prefetch K(mt+1)
        if (mt < 63) {
            const int m1 = mt * 64 + 64;
            for (int i = t; i < 1024; i += 256) {
                int r = i >> 4, c16 = i & 15;
                uint32_t doff = (uint32_t)(r * SQ + c16 * 16);
                cpa16(sb + SM_KH + doff, khb + (size_t)(m1 + r) * CI + c16 * 8);
                cpa16(sb + SM_KL + doff, klb + (size_t)(m1 + r) * CI + c16 * 8);
            }
            CP_COMMIT();
        }

        // ---- PV fused-split ----
        const uint32_t bGh = sb + ((mt & 1) ? SM_GH1 : SM_GH0) + gOff;
        const uint32_t bGl = bGh + 18432;
        #pragma unroll
        for (int kk = 0; kk < 4; kk++) {
            uint32_t ph[4], pl[4];
            ldsm4(ph, aPh + kk * 32);
            ldsm4(pl, aPl + kk * 32);
            #pragma unroll
            for (int np = 0; np < 8; np++) {
                uint32_t bh[4], bl[4];
                ldsm4(bh, bGh + np * (16 * SP) + kk * 32);
                ldsm4(bl, bGl + np * (16 * SP) + kk * 32);
                mma16816(yacc[2 * np],     ph, bh[0], bh[1]);
                mma16816(yacc[2 * np + 1], ph, bh[2], bh[3]);
                mma16816(yacc[2 * np],     ph, bl[0], bl[1]);
                mma16816(yacc[2 * np + 1], ph, bl[2], bl[3]);
                mma16816(yacc[2 * np],     pl, bh[0], bh[1]);
                mma16816(yacc[2 * np + 1], pl, bh[2], bh[3]);
            }
        }
    }

    // ---- normalize, split Y into smem (aliases Q region) ----
    {
        float rv0 = 1.f / lsum0, rv1 = 1.f / lsum1;
        #pragma unroll
        for (int n = 0; n < 16; n++) {
            float y0 = yacc[n][0] * rv0, y1 = yacc[n][1] * rv0;
            float y2 = yacc[n][2] * rv1, y3 = yacc[n][3] * rv1;
            float r0, r1;
            uint32_t hp = pkbf(y0, y1, &r0, &r1);
            uint32_t lp = pkbf2(r0, r1);
            uint32_t off = (uint32_t)((16 * w + g) * SQ + (8 * n + 2 * tc) * 2);
            *(uint32_t*)(smem + SM_YH + off) = hp;
            *(uint32_t*)(smem + SM_YL + off) = lp;
            hp = pkbf(y2, y3, &r0, &r1);
            lp = pkbf2(r0, r1);
            off += 8 * SQ;
            *(uint32_t*)(smem + SM_YH + off) = hp;
            *(uint32_t*)(smem + SM_YL + off) = lp;
        }
    }

    // ---- WY = W_w @ Y + W_b, two 128-channel halves ----
    const uint32_t aYh = sb + SM_YH + (uint32_t)((16 * w + lr) * SQ + lk);
    const uint32_t aYl = aYh + (SM_YL - SM_YH);
    const uint32_t bWh = sb + SM_WH + (uint32_t)(bn * SQ + bk);
    const uint32_t bWl = bWh + (SM_WL - SM_WH);
    float* WYb = g_WY + (size_t)b * CIN * NPOS + q0;

    #pragma unroll 1
    for (int h = 0; h < 2; h++) {
        __syncthreads();   // Y visible (h=0) / prev W reads done (h=1)
        const __nv_bfloat16* wh = g_Wh + (size_t)h * 128 * CI;
        const __nv_bfloat16* wl = g_Wl + (size_t)h * 128 * CI;
        for (int i = t; i < 2048; i += 256) {
            int r = i >> 4, c16 = i & 15;
            uint32_t off = (uint32_t)(r * SQ + c16 * 16);
            *(uint4*)(smem + SM_WH + off) = *(const uint4*)(wh + (size_t)r * CI + c16 * 8);
            *(uint4*)(smem + SM_WL + off) = *(const uint4*)(wl + (size_t)r * CI + c16 * 8);
        }
        __syncthreads();

        float wacc[16][4];
        #pragma unroll
        for (int n = 0; n < 16; n++)
            #pragma unroll
            for (int j = 0; j < 4; j++) wacc[n][j] = 0.f;

        #pragma unroll
        for (int kk = 0; kk < 8; kk++) {
            uint32_t ah[4], al[4];
            ldsm4(ah, aYh + kk * 32);
            ldsm4(al, aYl + kk * 32);
            #pragma unroll
            for (int np = 0; np < 8; np++) {
                uint32_t bh[4], bl[4];
                ldsm4(bh, bWh + np * (16 * SQ) + kk * 32);
                ldsm4(bl, bWl + np * (16 * SQ) + kk * 32);
                mma16816(wacc[2 * np],     ah, bh[0], bh[1]);
                mma16816(wacc[2 * np + 1], ah, bh[2], bh[3]);
                mma16816(wacc[2 * np],     ah, bl[0], bl[1]);
                mma16816(wacc[2 * np + 1], ah, bl[2], bl[3]);
                mma16816(wacc[2 * np],     al, bh[0], bh[1]);
                mma16816(wacc[2 * np + 1], al, bh[2], bh[3]);
            }
        }

        #pragma unroll
        for (int n = 0; n < 16; n++) {
            int o = h * 128 + 8 * n + 2 * tc;
            float b0 = __ldg(&W_b[o]);
            float b1 = __ldg(&W_b[o + 1]);
            int r0 = 16 * w + g;
            WYb[(size_t)o * NPOS + r0]           = wacc[n][0] + b0;
            WYb[(size_t)(o + 1) * NPOS + r0]     = wacc[n][1] + b1;
            WYb[(size_t)o * NPOS + r0 + 8]       = wacc[n][2] + b0;
            WYb[(size_t)(o + 1) * NPOS + r0 + 8] = wacc[n][3] + b1;
        }
    }
}

// =================================================================
// K3: BN statistics — partial pass (4 slices x 256 channels) + finalize
// =================================================================
__global__ __launch_bounds__(256) void stats_part_kernel()
{
    const int c = blockIdx.x;
    const int s = blockIdx.y;
    const int t = threadIdx.x;
    float sm = 0.f, ss = 0.f;
    for (int b = 2 * s; b < 2 * s + 2; b++) {
        const float* p = g_WY + ((size_t)b * CIN + c) * NPOS;
        for (int i = t; i < NPOS / 4; i += 256) {
            float4 v = *(const float4*)&p[4 * i];
            sm += v.x + v.y + v.z + v.w;
            ss += v.x * v.x + v.y * v.y + v.z * v.z + v.w * v.w;
        }
    }
    __shared__ float rs[256], rss[256];
    rs[t] = sm; rss[t] = ss;
    __syncthreads();
    for (int o = 128; o > 0; o >>= 1) {
        if (t < o) { rs[t] += rs[t + o]; rss[t] += rss[t + o]; }
        __syncthreads();
    }
    if (t == 0) {
        g_ps[s * CIN + c]  = rs[0];
        g_pss[s * CIN + c] = rss[0];
    }
}

__global__ __launch_bounds__(256) void stats_fin_kernel()
{
    const int c = threadIdx.x;
    float sm = g_ps[c] + g_ps[CIN + c] + g_ps[2 * CIN + c] + g_ps[3 * CIN + c];
    float ss = g_pss[c] + g_pss[CIN + c] + g_pss[2 * CIN + c] + g_pss[3 * CIN + c];
    const float inv = 1.f / (float)(BATCH * NPOS);
    float mean = sm * inv;
    float var  = ss * inv - mean * mean;
    g_mean[c] = mean;
    g_rstd[c] = rsqrtf(var + 1e-5f);
}

// =================================================================
// K4: z = (wy - mean)*rstd*gamma + beta + x
// =================================================================
__global__ __launch_bounds__(256) void final_kernel(
    const float* __restrict__ x,
    const float* __restrict__ gamma, const float* __restrict__ beta,
    float* __restrict__ z)
{
    size_t i4 = (size_t)blockIdx.x * 256 + threadIdx.x;
    size_t i  = i4 * 4;
    int c = (int)((i >> 12) & 255);
    float m = g_mean[c], r = g_rstd[c], ga = gamma[c], be = beta[c];
    float4 wy = *(const float4*)&g_WY[i];
    float4 xv = *(const float4*)&x[i];
    float4 o;
    o.x = (wy.x - m) * r * ga + be + xv.x;
    o.y = (wy.y - m) * r * ga + be + xv.y;
    o.z = (wy.z - m) * r * ga + be + xv.z;
    o.w = (wy.w - m) * r * ga + be + xv.w;
    *(float4*)&z[i] = o;
}

// =================================================================
extern "C" void kernel_launch(void* const* d_in, const int* in_sizes, int n_in,
                              void* d_out, int out_size)
{
    const float* x       = (const float*)d_in[0];
    const float* g_w     = (const float*)d_in[1];
    const float* g_b     = (const float*)d_in[2];
    const float* theta_w = (const float*)d_in[3];
    const float* theta_b = (const float*)d_in[4];
    const float* phi_w   = (const float*)d_in[5];
    const float* phi_b   = (const float*)d_in[6];
    const float* W_w     = (const float*)d_in[7];
    const float* W_b     = (const float*)d_in[8];
    const float* bn_g    = (const float*)d_in[9];
    const float* bn_b    = (const float*)d_in[10];
    float* z = (float*)d_out;

    cudaFuncSetAttribute(proj_npos_kernel, cudaFuncAttributeMaxDynamicSharedMemorySize, PJ_SMEM);
    cudaFuncSetAttribute(proj_chan_kernel, cudaFuncAttributeMaxDynamicSharedMemorySize, PG_SMEM);
    cudaFuncSetAttribute(attn_mma_kernel,  cudaFuncAttributeMaxDynamicSharedMemorySize, SMEM_BYTES);

    split_x_kernel<<<8192, 256>>>(x);
    split_wts_kernel<<<512, 256>>>(theta_w, phi_w, g_w, W_w);
    proj_npos_kernel<<<dim3(32, 8), 256, PJ_SMEM>>>(theta_b, phi_b);
    proj_chan_kernel<<<dim3(32, 8), 256, PG_SMEM>>>(g_b);
    attn_mma_kernel<<<dim3(32, 8), 256, SMEM_BYTES>>>(W_b);
    stats_part_kernel<<<dim3(256, 4), 256>>>();
    stats_fin_kernel<<<1, 256>>>();
    final_kernel<<<8192, 256>>>(x, bn_g, bn_b, z);
}

// round 7
// speedup vs baseline: 4.0667x; 1.1079x over previous
#include <cuda_runtime.h>
#include <cuda_bf16.h>
#include <math.h>
#include <stdint.h>

#define BATCH 8
#define CIN   256
#define CI    128
#define NPOS  4096

// ---------------- scratch (allocation-free: __device__ globals) ----------------
__device__ __align__(16) __nv_bfloat16 g_Xh [(size_t)BATCH * CIN * NPOS];  // x hi [b][c][n]
__device__ __align__(16) __nv_bfloat16 g_Xl [(size_t)BATCH * CIN * NPOS];
__device__ __align__(16) __nv_bfloat16 g_THh[(size_t)BATCH * NPOS * CI];   // theta [b][n][c]
__device__ __align__(16) __nv_bfloat16 g_THl[(size_t)BATCH * NPOS * CI];
__device__ __align__(16) __nv_bfloat16 g_PHh[(size_t)BATCH * NPOS * CI];   // phi   [b][n][c]
__device__ __align__(16) __nv_bfloat16 g_PHl[(size_t)BATCH * NPOS * CI];
__device__ __align__(16) __nv_bfloat16 g_Gh [(size_t)BATCH * CI * NPOS];   // g     [b][c][n]
__device__ __align__(16) __nv_bfloat16 g_Gl [(size_t)BATCH * CI * NPOS];
__device__ __align__(16) __nv_bfloat16 g_WQh[2 * CI * CIN];   // [theta_w ; phi_w] [256][256]
__device__ __align__(16) __nv_bfloat16 g_WQl[2 * CI * CIN];
__device__ __align__(16) __nv_bfloat16 g_WGh[CI * CIN];       // g_w [128][256]
__device__ __align__(16) __nv_bfloat16 g_WGl[CI * CIN];
__device__ __align__(16) __nv_bfloat16 g_Wh [CIN * CI];       // W_w [256][128]
__device__ __align__(16) __nv_bfloat16 g_Wl [CIN * CI];
__device__ float g_WY[(size_t)BATCH * CIN * NPOS];            // W(y) [b][o][n]
__device__ float g_ps[4 * CIN], g_pss[4 * CIN];
__device__ float g_mean[CIN];
__device__ float g_rstd[CIN];

// ---------------- helpers ----------------
__device__ __forceinline__ uint32_t s2u(const void* p) {
    uint32_t a;
    asm("{ .reg .u64 t; cvta.to.shared.u64 t, %1; cvt.u32.u64 %0, t; }" : "=r"(a) : "l"(p));
    return a;
}
__device__ __forceinline__ void ldsm4(uint32_t r[4], uint32_t addr) {
    asm volatile("ldmatrix.sync.aligned.m8n8.x4.shared.b16 {%0,%1,%2,%3}, [%4];"
                 : "=r"(r[0]), "=r"(r[1]), "=r"(r[2]), "=r"(r[3]) : "r"(addr));
}
__device__ __forceinline__ void ldsm4t(uint32_t r[4], uint32_t addr) {
    asm volatile("ldmatrix.sync.aligned.m8n8.x4.trans.shared.b16 {%0,%1,%2,%3}, [%4];"
                 : "=r"(r[0]), "=r"(r[1]), "=r"(r[2]), "=r"(r[3]) : "r"(addr));
}
__device__ __forceinline__ void mma16816(float d[4], const uint32_t a[4],
                                         uint32_t b0, uint32_t b1) {
    asm volatile(
        "mma.sync.aligned.m16n8k16.row.col.f32.bf16.bf16.f32 "
        "{%0,%1,%2,%3}, {%4,%5,%6,%7}, {%8,%9}, {%0,%1,%2,%3};"
        : "+f"(d[0]), "+f"(d[1]), "+f"(d[2]), "+f"(d[3])
        : "r"(a[0]), "r"(a[1]), "r"(a[2]), "r"(a[3]), "r"(b0), "r"(b1));
}
__device__ __forceinline__ void cpa16(uint32_t dst, const void* src) {
    asm volatile("cp.async.cg.shared.global [%0], [%1], 16;" :: "r"(dst), "l"(src));
}
#define CP_COMMIT() asm volatile("cp.async.commit_group;" ::: "memory")
#define CP_WAIT0()  asm volatile("cp.async.wait_group 0;" ::: "memory")
#define CP_WAIT1()  asm volatile("cp.async.wait_group 1;" ::: "memory")

__device__ __forceinline__ uint32_t pkbf(float a, float b, float* ra, float* rb) {
    __nv_bfloat16 ha = __float2bfloat16(a);
    __nv_bfloat16 hb = __float2bfloat16(b);
    *ra = a - __bfloat162float(ha);
    *rb = b - __bfloat162float(hb);
    return (uint32_t)__bfloat16_as_ushort(ha) | ((uint32_t)__bfloat16_as_ushort(hb) << 16);
}
__device__ __forceinline__ uint32_t pkbf2(float a, float b) {
    return (uint32_t)__bfloat16_as_ushort(__float2bfloat16(a)) |
           ((uint32_t)__bfloat16_as_ushort(__float2bfloat16(b)) << 16);
}

// =================================================================
// K0a: split x -> bf16 hi/lo
// =================================================================
__global__ __launch_bounds__(256) void split_x_kernel(const float* __restrict__ x)
{
    size_t i = ((size_t)blockIdx.x * 256 + threadIdx.x) * 4;
    float4 v = *(const float4*)&x[i];
    float r0, r1, r2, r3;
    uint32_t h01 = pkbf(v.x, v.y, &r0, &r1);
    uint32_t h23 = pkbf(v.z, v.w, &r2, &r3);
    *(uint2*)&g_Xh[i] = make_uint2(h01, h23);
    *(uint2*)&g_Xl[i] = make_uint2(pkbf2(r0, r1), pkbf2(r2, r3));
}

// =================================================================
// K0b: split all weights -> bf16 hi/lo
// =================================================================
__global__ __launch_bounds__(256) void split_wts_kernel(
    const float* __restrict__ thw, const float* __restrict__ phw,
    const float* __restrict__ gw,  const float* __restrict__ Ww)
{
    int i = blockIdx.x * 256 + threadIdx.x;   // 0..131071
    int which = i >> 15, j = i & 32767;
    float v;
    __nv_bfloat16 *dh, *dl;
    int o;
    if (which == 0)      { v = thw[j]; dh = g_WQh; dl = g_WQl; o = j; }
    else if (which == 1) { v = phw[j]; dh = g_WQh; dl = g_WQl; o = 32768 + j; }
    else if (which == 2) { v = gw[j];  dh = g_WGh; dl = g_WGl; o = j; }
    else                 { v = Ww[j];  dh = g_Wh;  dl = g_Wl;  o = j; }
    __nv_bfloat16 h = __float2bfloat16(v);
    dh[o] = h;
    dl[o] = __float2bfloat16(v - __bfloat162float(h));
}

// =================================================================
// K1a: theta/phi projection (HMMA). out[n][o] = sum_c x[c][n]*w[o][c] + b[o]
// =================================================================
#define PSQ 272
#define PSW 80
#define PJ_XH 0
#define PJ_XL 8704
#define PJ_WH 17408
#define PJ_WL 37888
#define PJ_BUF 58368
#define PJ_BIAS 116736
#define PJ_SMEM 117760

__global__ __launch_bounds__(256, 1) void proj_npos_kernel(
    const float* __restrict__ th_b, const float* __restrict__ ph_b)
{
    extern __shared__ __align__(16) char smem[];
    const uint32_t sb = s2u(smem);
    const int t = threadIdx.x, w = t >> 5, L = t & 31;
    const int g = L >> 2, tc = L & 3;
    const int b = blockIdx.y;
    const int n0 = blockIdx.x * 128;

    float* bias = (float*)(smem + PJ_BIAS);
    bias[t] = (t < 128) ? th_b[t] : ph_b[t - 128];

    const __nv_bfloat16* xh = g_Xh + (size_t)b * CIN * NPOS + n0;
    const __nv_bfloat16* xl = g_Xl + (size_t)b * CIN * NPOS + n0;

    const uint32_t aoff = (uint32_t)(((L & 7) + ((L >> 4) & 1) * 8) * PSQ + 32 * w +
                                     ((L >> 3) & 1) * 16);
    const uint32_t boff = (uint32_t)(((L >> 4) * 8 + (L & 7)) * PSW + ((L >> 3) & 1) * 16);

    float acc[32][4];
    #pragma unroll
    for (int j = 0; j < 32; j++)
        #pragma unroll
        for (int k = 0; k < 4; k++) acc[j][k] = 0.f;

    {
        uint32_t base = sb;
        for (int i = t; i < 512; i += 256) {
            int r = i >> 4, c16 = i & 15;
            uint32_t doff = (uint32_t)(r * PSQ + c16 * 16);
            cpa16(base + PJ_XH + doff, xh + (size_t)r * NPOS + c16 * 8);
            cpa16(base + PJ_XL + doff, xl + (size_t)r * NPOS + c16 * 8);
        }
        for (int i = t; i < 1024; i += 256) {
            int r = i >> 2, c4 = i & 3;
            uint32_t doff = (uint32_t)(r * PSW + c4 * 16);
            cpa16(base + PJ_WH + doff, g_WQh + (size_t)r * CIN + c4 * 8);
            cpa16(base + PJ_WL + doff, g_WQl + (size_t)r * CIN + c4 * 8);
        }
        CP_COMMIT();
    }

    #pragma unroll 1
    for (int ch = 0; ch < 8; ch++) {
        if (ch < 7) {
            int c0 = (ch + 1) * 32;
            uint32_t base = sb + ((ch + 1) & 1) * PJ_BUF;
            for (int i = t; i < 512; i += 256) {
                int r = i >> 4, c16 = i & 15;
                uint32_t doff = (uint32_t)(r * PSQ + c16 * 16);
                cpa16(base + PJ_XH + doff, xh + (size_t)(c0 + r) * NPOS + c16 * 8);
                cpa16(base + PJ_XL + doff, xl + (size_t)(c0 + r) * NPOS + c16 * 8);
            }
            for (int i = t; i < 1024; i += 256) {
                int r = i >> 2, c4 = i & 3;
                uint32_t doff = (uint32_t)(r * PSW + c4 * 16);
                cpa16(base + PJ_WH + doff, g_WQh + (size_t)r * CIN + c0 + c4 * 8);
                cpa16(base + PJ_WL + doff, g_WQl + (size_t)r * CIN + c0 + c4 * 8);
            }
            CP_COMMIT();
            CP_WAIT1();
        } else {
            CP_WAIT0();
        }
        __syncthreads();
        const uint32_t xbase = sb + (ch & 1) * PJ_BUF;
        const uint32_t aB = xbase + PJ_XH + aoff;
        const uint32_t bB = xbase + PJ_WH + boff;
        #pragma unroll
        for (int kk = 0; kk < 2; kk++) {
            uint32_t ah[4], al[4];
            ldsm4t(ah, aB + kk * 16 * PSQ);
            ldsm4t(al, aB + 8704 + kk * 16 * PSQ);
            #pragma unroll
            for (int np = 0; np < 16; np++) {
                uint32_t bh[4], bl[4];
                ldsm4(bh, bB + np * (16 * PSW) + kk * 32);
                ldsm4(bl, bB + 20480 + np * (16 * PSW) + kk * 32);
                mma16816(acc[2 * np],     ah, bh[0], bh[1]);
                mma16816(acc[2 * np + 1], ah, bh[2], bh[3]);
                mma16816(acc[2 * np],     ah, bl[0], bl[1]);
                mma16816(acc[2 * np + 1], ah, bl[2], bl[3]);
                mma16816(acc[2 * np],     al, bh[0], bh[1]);
                mma16816(acc[2 * np + 1], al, bh[2], bh[3]);
            }
        }
        __syncthreads();
    }

    const int nrow = n0 + 16 * w + g;
    const size_t rb0 = ((size_t)b * NPOS + nrow) * CI;
    const size_t rb1 = rb0 + (size_t)8 * CI;
    #pragma unroll
    for (int j = 0; j < 32; j++) {
        int o = 8 * j + 2 * tc;
        float b0 = bias[o], b1 = bias[o + 1];
        __nv_bfloat16 *dh, *dl;
        int c;
        if (o < 128) { dh = g_THh; dl = g_THl; c = o; }
        else         { dh = g_PHh; dl = g_PHl; c = o - 128; }
        float r0, r1;
        uint32_t hp = pkbf(acc[j][0] + b0, acc[j][1] + b1, &r0, &r1);
        uint32_t lp = pkbf2(r0, r1);
        *(uint32_t*)(dh + rb0 + c) = hp;
        *(uint32_t*)(dl + rb0 + c) = lp;
        hp = pkbf(acc[j][2] + b0, acc[j][3] + b1, &r0, &r1);
        lp = pkbf2(r0, r1);
        *(uint32_t*)(dh + rb1 + c) = hp;
        *(uint32_t*)(dl + rb1 + c) = lp;
    }
}

// =================================================================
// K1b: g projection (HMMA). out[o][n] = sum_c w[o][c]*x[c][n] + b[o]
// =================================================================
#define PG_XH 0
#define PG_XL 8704
#define PG_WH 17408
#define PG_WL 27648
#define PG_BUF 37888
#define PG_BIAS 75776
#define PG_SMEM 76800

__global__ __launch_bounds__(256, 1) void proj_chan_kernel(const float* __restrict__ g_b)
{
    extern __shared__ __align__(16) char smem[];
    const uint32_t sb = s2u(smem);
    const int t = threadIdx.x, w = t >> 5, L = t & 31;
    const int g = L >> 2, tc = L & 3;
    const int b = blockIdx.y;
    const int n0 = blockIdx.x * 128;

    float* bias = (float*)(smem + PG_BIAS);
    if (t < 128) bias[t] = g_b[t];

    const __nv_bfloat16* xh = g_Xh + (size_t)b * CIN * NPOS + n0;
    const __nv_bfloat16* xl = g_Xl + (size_t)b * CIN * NPOS + n0;

    const uint32_t aoff = (uint32_t)((16 * w + (L & 7) + ((L >> 3) & 1) * 8) * PSW +
                                     (L >> 4) * 16);
    const uint32_t boff = (uint32_t)(((L & 7) + ((L >> 3) & 1) * 8) * PSQ + (L >> 4) * 16);

    float acc[16][4];
    #pragma unroll
    for (int j = 0; j < 16; j++)
        #pragma unroll
        for (int k = 0; k < 4; k++) acc[j][k] = 0.f;

    {
        uint32_t base = sb;
        for (int i = t; i < 512; i += 256) {
            int r = i >> 4, c16 = i & 15;
            uint32_t doff = (uint32_t)(r * PSQ + c16 * 16);
            cpa16(base + PG_XH + doff, xh + (size_t)r * NPOS + c16 * 8);
            cpa16(base + PG_XL + doff, xl + (size_t)r * NPOS + c16 * 8);
        }
        for (int i = t; i < 512; i += 256) {
            int r = i >> 2, c4 = i & 3;
            uint32_t doff = (uint32_t)(r * PSW + c4 * 16);
            cpa16(base + PG_WH + doff, g_WGh + (size_t)r * CIN + c4 * 8);
            cpa16(base + PG_WL + doff, g_WGl + (size_t)r * CIN + c4 * 8);
        }
        CP_COMMIT();
    }

    #pragma unroll 1
    for (int ch = 0; ch < 8; ch++) {
        if (ch < 7) {
            int c0 = (ch + 1) * 32;
            uint32_t base = sb + ((ch + 1) & 1) * PG_BUF;
            for (int i = t; i < 512; i += 256) {
                int r = i >> 4, c16 = i & 15;
                uint32_t doff = (uint32_t)(r * PSQ + c16 * 16);
                cpa16(base + PG_XH + doff, xh + (size_t)(c0 + r) * NPOS + c16 * 8);
                cpa16(base + PG_XL + doff, xl + (size_t)(c0 + r) * NPOS + c16 * 8);
            }
            for (int i = t; i < 512; i += 256) {
                int r = i >> 2, c4 = i & 3;
                uint32_t doff = (uint32_t)(r * PSW + c4 * 16);
                cpa16(base + PG_WH + doff, g_WGh + (size_t)r * CIN + c0 + c4 * 8);
                cpa16(base + PG_WL + doff, g_WGl + (size_t)r * CIN + c0 + c4 * 8);
            }
            CP_COMMIT();
            CP_WAIT1();
        } else {
            CP_WAIT0();
        }
        __syncthreads();
        const uint32_t xbase = sb + (ch & 1) * PG_BUF;
        const uint32_t aB = xbase + PG_WH + aoff;
        const uint32_t bB = xbase + PG_XH + boff;
        #pragma unroll
        for (int kk = 0; kk < 2; kk++) {
            uint32_t ah[4], al[4];
            ldsm4(ah, aB + kk * 32);
            ldsm4(al, aB + 10240 + kk * 32);
            #pragma unroll
            for (int np = 0; np < 8; np++) {
                uint32_t bh[4], bl[4];
                ldsm4t(bh, bB + np * 32 + kk * 16 * PSQ);
                ldsm4t(bl, bB + 8704 + np * 32 + kk * 16 * PSQ);
                mma16816(acc[2 * np],     ah, bh[0], bh[1]);
                mma16816(acc[2 * np + 1], ah, bh[2], bh[3]);
                mma16816(acc[2 * np],     ah, bl[0], bl[1]);
                mma16816(acc[2 * np + 1], ah, bl[2], bl[3]);
                mma16816(acc[2 * np],     al, bh[0], bh[1]);
                mma16816(acc[2 * np + 1], al, bh[2], bh[3]);
            }
        }
        __syncthreads();
    }

    const int o = 16 * w + g;
    const float b0 = bias[o], b8 = bias[o + 8];
    #pragma unroll
    for (int j = 0; j < 16; j++) {
        int n = 16 * (j >> 1) + 8 * (j & 1) + 2 * tc;
        size_t a0 = ((size_t)b * CI + o) * NPOS + n0 + n;
        size_t a8 = a0 + (size_t)8 * NPOS;
        float r0, r1;
        uint32_t hp = pkbf(acc[j][0] + b0, acc[j][1] + b0, &r0, &r1);
        uint32_t lp = pkbf2(r0, r1);
        *(uint32_t*)(g_Gh + a0) = hp;
        *(uint32_t*)(g_Gl + a0) = lp;
        hp = pkbf(acc[j][2] + b8, acc[j][3] + b8, &r0, &r1);
        lp = pkbf2(r0, r1);
        *(uint32_t*)(g_Gh + a8) = hp;
        *(uint32_t*)(g_Gl + a8) = lp;
    }
}

// =================================================================
// K2: HMMA attention — FA2 register pipeline.
// P and Y never touch smem (C-frag == A-frag reinterpretation).
// K and G double-buffered; ONE __syncthreads per key-tile iteration.
// =================================================================
#define SQ 272
#define SP 144
#define SM_QH  0
#define SM_QL  34816
#define SM_K0  69632            // K buf0: hi @0, lo @+17408
#define SM_K1  104448           // K buf1
#define SM_G0  139264           // G buf0: hi @0, lo @+18432
#define SM_G1  176128           // G buf1
#define SMEM_BYTES 212992
// epilogue aliases (inside K/G region)
#define SM_WHB 69632
#define SM_WLB 104448

__global__ __launch_bounds__(256, 1) void attn_mma_kernel(const float* __restrict__ W_b)
{
    extern __shared__ __align__(16) char smem[];
    const uint32_t sb = s2u(smem);
    const int t = threadIdx.x, w = t >> 5, L = t & 31;
    const int b = blockIdx.y;
    const int q0 = blockIdx.x * 128;
    const int g  = L >> 2, tc = L & 3;

    const __nv_bfloat16* qh  = g_THh + ((size_t)b * NPOS + q0) * CI;
    const __nv_bfloat16* ql  = g_THl + ((size_t)b * NPOS + q0) * CI;
    const __nv_bfloat16* khb = g_PHh + (size_t)b * NPOS * CI;
    const __nv_bfloat16* klb = g_PHl + (size_t)b * NPOS * CI;
    const __nv_bfloat16* ghb = g_Gh + (size_t)b * CI * NPOS;
    const __nv_bfloat16* glb = g_Gl + (size_t)b * CI * NPOS;

    // prologue: Q, K(0)->buf0, G(0)->buf0
    for (int i = t; i < 2048; i += 256) {
        int r = i >> 4, c16 = i & 15;
        uint32_t doff = (uint32_t)(r * SQ + c16 * 16);
        cpa16(sb + SM_QH + doff, qh + (size_t)r * CI + c16 * 8);
        cpa16(sb + SM_QL + doff, ql + (size_t)r * CI + c16 * 8);
    }
    for (int i = t; i < 1024; i += 256) {
        int r = i >> 4, c16 = i & 15;
        uint32_t doff = (uint32_t)(r * SQ + c16 * 16);
        cpa16(sb + SM_K0 + doff, khb + (size_t)r * CI + c16 * 8);
        cpa16(sb + SM_K0 + 17408 + doff, klb + (size_t)r * CI + c16 * 8);
    }
    for (int i = t; i < 1024; i += 256) {
        int r = i >> 3, c8 = i & 7;
        uint32_t doff = (uint32_t)(r * SP + c8 * 16);
        cpa16(sb + SM_G0 + doff, ghb + (size_t)r * NPOS + c8 * 8);
        cpa16(sb + SM_G0 + 18432 + doff, glb + (size_t)r * NPOS + c8 * 8);
    }
    CP_COMMIT();

    // per-lane ldmatrix bases
    const int lr = ((L >> 3) & 1) * 8 + (L & 7);
    const int lk = (L >> 4) * 16;
    const int bn = (L >> 4) * 8 + (L & 7);
    const int bk = ((L >> 3) & 1) * 16;

    const uint32_t aQh = sb + SM_QH + (uint32_t)((16 * w + lr) * SQ + lk);
    const uint32_t aQl = aQh + (SM_QL - SM_QH);
    const uint32_t kOff = (uint32_t)(bn * SQ + bk);
    const uint32_t gOff = (uint32_t)(bn * SP + bk);

    float yacc[16][4];
    #pragma unroll
    for (int n = 0; n < 16; n++)
        #pragma unroll
        for (int j = 0; j < 4; j++) yacc[n][j] = 0.f;
    float ls0 = 0.f, ls1 = 0.f;

    #pragma unroll 1
    for (int mt = 0; mt < NPOS / 64; mt++) {
        CP_WAIT0();
        __syncthreads();   // K(mt),G(mt) ready; everyone done with prev buffers

        // prefetch K(mt+1), G(mt+1) into alternate buffers
        if (mt < 63) {
            const int m1 = mt * 64 + 64;
            const uint32_t kdst = sb + (((mt + 1) & 1) ? SM_K1 : SM_K0);
            const uint32_t gdst = sb + (((mt + 1) & 1) ? SM_G1 : SM_G0);
            for (int i = t; i < 1024; i += 256) {
                int r = i >> 4, c16 = i & 15;
                uint32_t doff = (uint32_t)(r * SQ + c16 * 16);
                cpa16(kdst + doff, khb + (size_t)(m1 + r) * CI + c16 * 8);
                cpa16(kdst + 17408 + doff, klb + (size_t)(m1 + r) * CI + c16 * 8);
            }
            for (int i = t; i < 1024; i += 256) {
                int r = i >> 3, c8 = i & 7;
                uint32_t doff = (uint32_t)(r * SP + c8 * 16);
                cpa16(gdst + doff, ghb + (size_t)r * NPOS + m1 + c8 * 8);
                cpa16(gdst + 18432 + doff, glb + (size_t)r * NPOS + m1 + c8 * 8);
            }
            CP_COMMIT();
        }

        // ---- QK fused-split from K buffer (mt&1) ----
        const uint32_t bKh = sb + ((mt & 1) ? SM_K1 : SM_K0) + kOff;
        const uint32_t bKl = bKh + 17408;
        float acc[8][4];
        #pragma unroll
        for (int n = 0; n < 8; n++)
            #pragma unroll
            for (int j = 0; j < 4; j++) acc[n][j] = 0.f;
        #pragma unroll
        for (int kk = 0; kk < 8; kk++) {
            uint32_t ah[4], al[4];
            ldsm4(ah, aQh + kk * 32);
            ldsm4(al, aQl + kk * 32);
            #pragma unroll
            for (int np = 0; np < 4; np++) {
                uint32_t bh[4], bl[4];
                ldsm4(bh, bKh + np * (16 * SQ) + kk * 32);
                ldsm4(bl, bKl + np * (16 * SQ) + kk * 32);
                mma16816(acc[2 * np],     ah, bh[0], bh[1]);
                mma16816(acc[2 * np + 1], ah, bh[2], bh[3]);
                mma16816(acc[2 * np],     ah, bl[0], bl[1]);
                mma16816(acc[2 * np + 1], ah, bl[2], bl[3]);
                mma16816(acc[2 * np],     al, bh[0], bh[1]);
                mma16816(acc[2 * np + 1], al, bh[2], bh[3]);
            }
        }

        // ---- softmax: unnormalized exp, pack P directly into A-fragments ----
        // C-frag (row g/g+8, col 8n+2tc) == A-frag chunk kk=n>>1:
        //   n even -> a0,a1 ; n odd -> a2,a3
        uint32_t pfh[4][4], pfl[4][4];
        #pragma unroll
        for (int n = 0; n < 8; n++) {
            float p0 = __expf(acc[n][0]);
            float p1 = __expf(acc[n][1]);
            float p2 = __expf(acc[n][2]);
            float p3 = __expf(acc[n][3]);
            ls0 += p0 + p1;
            ls1 += p2 + p3;
            float r0, r1, r2, r3;
            uint32_t h01 = pkbf(p0, p1, &r0, &r1);
            uint32_t h23 = pkbf(p2, p3, &r2, &r3);
            int kk = n >> 1, e = (n & 1) * 2;
            pfh[kk][e]     = h01;
            pfh[kk][e + 1] = h23;
            pfl[kk][e]     = pkbf2(r0, r1);
            pfl[kk][e + 1] = pkbf2(r2, r3);
        }

        // ---- PV fused-split from G buffer (mt&1); P A-frags in registers ----
        const uint32_t bGh = sb + ((mt & 1) ? SM_G1 : SM_G0) + gOff;
        const uint32_t bGl = bGh + 18432;
        #pragma unroll
        for (int kk = 0; kk < 4; kk++) {
            #pragma unroll
            for (int np = 0; np < 8; np++) {
                uint32_t bh[4], bl[4];
                ldsm4(bh, bGh + np * (16 * SP) + kk * 32);
                ldsm4(bl, bGl + np * (16 * SP) + kk * 32);
                mma16816(yacc[2 * np],     pfh[kk], bh[0], bh[1]);
                mma16816(yacc[2 * np + 1], pfh[kk], bh[2], bh[3]);
                mma16816(yacc[2 * np],     pfh[kk], bl[0], bl[1]);
                mma16816(yacc[2 * np + 1], pfh[kk], bl[2], bl[3]);
                mma16816(yacc[2 * np],     pfl[kk], bh[0], bh[1]);
                mma16816(yacc[2 * np + 1], pfl[kk], bh[2], bh[3]);
            }
        }
    }

    // ---- finalize row sums (lanes tc 0..3 hold disjoint cols) ----
    ls0 += __shfl_xor_sync(0xffffffffu, ls0, 1);
    ls0 += __shfl_xor_sync(0xffffffffu, ls0, 2);
    ls1 += __shfl_xor_sync(0xffffffffu, ls1, 1);
    ls1 += __shfl_xor_sync(0xffffffffu, ls1, 2);

    // ---- normalize Y, pack directly into W-conv A-fragments (k = channel) ----
    uint32_t yfh[8][4], yfl[8][4];
    {
        float rv0 = 1.f / ls0, rv1 = 1.f / ls1;
        #pragma unroll
        for (int n = 0; n < 16; n++) {
            float y0 = yacc[n][0] * rv0, y1 = yacc[n][1] * rv0;
            float y2 = yacc[n][2] * rv1, y3 = yacc[n][3] * rv1;
            float r0, r1, r2, r3;
            uint32_t h01 = pkbf(y0, y1, &r0, &r1);
            uint32_t h23 = pkbf(y2, y3, &r2, &r3);
            int kk = n >> 1, e = (n & 1) * 2;
            yfh[kk][e]     = h01;
            yfh[kk][e + 1] = h23;
            yfl[kk][e]     = pkbf2(r0, r1);
            yfl[kk][e + 1] = pkbf2(r2, r3);
        }
    }

    // ---- WY = W_w @ Y + W_b, two 128-channel halves (W staged in K/G space) ----
    const uint32_t bWh = sb + SM_WHB + (uint32_t)(bn * SQ + bk);
    const uint32_t bWl = sb + SM_WLB + (uint32_t)(bn * SQ + bk);
    float* WYb = g_WY + (size_t)b * CIN * NPOS + q0;

    #pragma unroll 1
    for (int h = 0; h < 2; h++) {
        __syncthreads();   // all K/G (h=0) or prev-W (h=1) reads done
        const __nv_bfloat16* wh = g_Wh + (size_t)h * 128 * CI;
        const __nv_bfloat16* wl = g_Wl + (size_t)h * 128 * CI;
        for (int i = t; i < 2048; i += 256) {
            int r = i >> 4, c16 = i & 15;
            uint32_t off = (uint32_t)(r * SQ + c16 * 16);
            *(uint4*)(smem + SM_WHB + off) = *(const uint4*)(wh + (size_t)r * CI + c16 * 8);
            *(uint4*)(smem + SM_WLB + off) = *(const uint4*)(wl + (size_t)r * CI + c16 * 8);
        }
        __syncthreads();

        float wacc[16][4];
        #pragma unroll
        for (int n = 0; n < 16; n++)
            #pragma unroll
            for (int j = 0; j < 4; j++) wacc[n][j] = 0.f;

        #pragma unroll
        for (int kk = 0; kk < 8; kk++) {
            #pragma unroll
            for (int np = 0; np < 8; np++) {
                uint32_t bh[4], bl[4];
                ldsm4(bh, bWh + np * (16 * SQ) + kk * 32);
                ldsm4(bl, bWl + np * (16 * SQ) + kk * 32);
                mma16816(wacc[2 * np],     yfh[kk], bh[0], bh[1]);
                mma16816(wacc[2 * np + 1], yfh[kk], bh[2], bh[3]);
                mma16816(wacc[2 * np],     yfh[kk], bl[0], bl[1]);
                mma16816(wacc[2 * np + 1], yfh[kk], bl[2], bl[3]);
                mma16816(wacc[2 * np],     yfl[kk], bh[0], bh[1]);
                mma16816(wacc[2 * np + 1], yfl[kk], bh[2], bh[3]);
            }
        }

        #pragma unroll
        for (int n = 0; n < 16; n++) {
            int o = h * 128 + 8 * n + 2 * tc;
            float b0 = __ldg(&W_b[o]);
            float b1 = __ldg(&W_b[o + 1]);
            int r0 = 16 * w + g;
            WYb[(size_t)o * NPOS + r0]           = wacc[n][0] + b0;
            WYb[(size_t)(o + 1) * NPOS + r0]     = wacc[n][1] + b1;
            WYb[(size_t)o * NPOS + r0 + 8]       = wacc[n][2] + b0;
            WYb[(size_t)(o + 1) * NPOS + r0 + 8] = wacc[n][3] + b1;
        }
    }
}

// =================================================================
// K3: BN statistics — partial pass + finalize
// =================================================================
__global__ __launch_bounds__(256) void stats_part_kernel()
{
    const int c = blockIdx.x;
    const int s = blockIdx.y;
    const int t = threadIdx.x;
    float sm = 0.f, ss = 0.f;
    for (int b = 2 * s; b < 2 * s + 2; b++) {
        const float* p = g_WY + ((size_t)b * CIN + c) * NPOS;
        for (int i = t; i < NPOS / 4; i += 256) {
            float4 v = *(const float4*)&p[4 * i];
            sm += v.x + v.y + v.z + v.w;
            ss += v.x * v.x + v.y * v.y + v.z * v.z + v.w * v.w;
        }
    }
    __shared__ float rs[256], rss[256];
    rs[t] = sm; rss[t] = ss;
    __syncthreads();
    for (int o = 128; o > 0; o >>= 1) {
        if (t < o) { rs[t] += rs[t + o]; rss[t] += rss[t + o]; }
        __syncthreads();
    }
    if (t == 0) {
        g_ps[s * CIN + c]  = rs[0];
        g_pss[s * CIN + c] = rss[0];
    }
}

__global__ __launch_bounds__(256) void stats_fin_kernel()
{
    const int c = threadIdx.x;
    float sm = g_ps[c] + g_ps[CIN + c] + g_ps[2 * CIN + c] + g_ps[3 * CIN + c];
    float ss = g_pss[c] + g_pss[CIN + c] + g_pss[2 * CIN + c] + g_pss[3 * CIN + c];
    const float inv = 1.f / (float)(BATCH * NPOS);
    float mean = sm * inv;
    float var  = ss * inv - mean * mean;
    g_mean[c] = mean;
    g_rstd[c] = rsqrtf(var + 1e-5f);
}

// =================================================================
// K4: z = (wy - mean)*rstd*gamma + beta + x
// =================================================================
__global__ __launch_bounds__(256) void final_kernel(
    const float* __restrict__ x,
    const float* __restrict__ gamma, const float* __restrict__ beta,
    float* __restrict__ z)
{
    size_t i4 = (size_t)blockIdx.x * 256 + threadIdx.x;
    size_t i  = i4 * 4;
    int c = (int)((i >> 12) & 255);
    float m = g_mean[c], r = g_rstd[c], ga = gamma[c], be = beta[c];
    float4 wy = *(const float4*)&g_WY[i];
    float4 xv = *(const float4*)&x[i];
    float4 o;
    o.x = (wy.x - m) * r * ga + be + xv.x;
    o.y = (wy.y - m) * r * ga + be + xv.y;
    o.z = (wy.z - m) * r * ga + be + xv.z;
    o.w = (wy.w - m) * r * ga + be + xv.w;
    *(float4*)&z[i] = o;
}

// =================================================================
extern "C" void kernel_launch(void* const* d_in, const int* in_sizes, int n_in,
                              void* d_out, int out_size)
{
    const float* x       = (const float*)d_in[0];
    const float* g_w     = (const float*)d_in[1];
    const float* g_b     = (const float*)d_in[2];
    const float* theta_w = (const float*)d_in[3];
    const float* theta_b = (const float*)d_in[4];
    const float* phi_w   = (const float*)d_in[5];
    const float* phi_b   = (const float*)d_in[6];
    const float* W_w     = (const float*)d_in[7];
    const float* W_b     = (const float*)d_in[8];
    const float* bn_g    = (const float*)d_in[9];
    const float* bn_b    = (const float*)d_in[10];
    float* z = (float*)d_out;

    cudaFuncSetAttribute(proj_npos_kernel, cudaFuncAttributeMaxDynamicSharedMemorySize, PJ_SMEM);
    cudaFuncSetAttribute(proj_chan_kernel, cudaFuncAttributeMaxDynamicSharedMemorySize, PG_SMEM);
    cudaFuncSetAttribute(attn_mma_kernel,  cudaFuncAttributeMaxDynamicSharedMemorySize, SMEM_BYTES);

    split_x_kernel<<<8192, 256>>>(x);
    split_wts_kernel<<<512, 256>>>(theta_w, phi_w, g_w, W_w);
    proj_npos_kernel<<<dim3(32, 8), 256, PJ_SMEM>>>(theta_b, phi_b);
    proj_chan_kernel<<<dim3(32, 8), 256, PG_SMEM>>>(g_b);
    attn_mma_kernel<<<dim3(32, 8), 256, SMEM_BYTES>>>(W_b);
    stats_part_kernel<<<dim3(256, 4), 256>>>();
    stats_fin_kernel<<<1, 256>>>();
    final_kernel<<<8192, 256>>>(x, bn_g, bn_b, z);
}

// round 8
// speedup vs baseline: 5.3627x; 1.3187x over previous
#include <cuda_runtime.h>
#include <cuda_bf16.h>
#include <cuda_fp16.h>
#include <math.h>
#include <stdint.h>

#define BATCH 8
#define CIN   256
#define CI    128
#define NPOS  4096

// ---------------- scratch (allocation-free: __device__ globals) ----------------
__device__ __align__(16) __nv_bfloat16 g_Xh [(size_t)BATCH * CIN * NPOS];  // x hi [b][c][n]
__device__ __align__(16) __nv_bfloat16 g_Xl [(size_t)BATCH * CIN * NPOS];
__device__ __align__(16) __nv_bfloat16 g_THh[(size_t)BATCH * NPOS * CI];   // theta [b][n][c]
__device__ __align__(16) __nv_bfloat16 g_THl[(size_t)BATCH * NPOS * CI];
__device__ __align__(16) __nv_bfloat16 g_PHh[(size_t)BATCH * NPOS * CI];   // phi   [b][n][c]
__device__ __align__(16) __nv_bfloat16 g_PHl[(size_t)BATCH * NPOS * CI];
__device__ __align__(16) __half        g_G  [(size_t)BATCH * CI * NPOS];   // g fp16 [b][c][n]
__device__ __align__(16) __nv_bfloat16 g_WQh[2 * CI * CIN];   // [theta_w ; phi_w]
__device__ __align__(16) __nv_bfloat16 g_WQl[2 * CI * CIN];
__device__ __align__(16) __nv_bfloat16 g_WGh[CI * CIN];       // g_w [128][256]
__device__ __align__(16) __nv_bfloat16 g_WGl[CI * CIN];
__device__ __align__(16) __half        g_Whalf[CIN * CI];     // W_w fp16 [256][128]
__device__ float g_WY[(size_t)BATCH * CIN * NPOS];            // W(y) [b][o][n]
__device__ float g_ps[4 * CIN], g_pss[4 * CIN];
__device__ float g_mean[CIN];
__device__ float g_rstd[CIN];

// ---------------- helpers ----------------
__device__ __forceinline__ uint32_t s2u(const void* p) {
    uint32_t a;
    asm("{ .reg .u64 t; cvta.to.shared.u64 t, %1; cvt.u32.u64 %0, t; }" : "=r"(a) : "l"(p));
    return a;
}
__device__ __forceinline__ void ldsm4(uint32_t r[4], uint32_t addr) {
    asm volatile("ldmatrix.sync.aligned.m8n8.x4.shared.b16 {%0,%1,%2,%3}, [%4];"
                 : "=r"(r[0]), "=r"(r[1]), "=r"(r[2]), "=r"(r[3]) : "r"(addr));
}
__device__ __forceinline__ void ldsm4t(uint32_t r[4], uint32_t addr) {
    asm volatile("ldmatrix.sync.aligned.m8n8.x4.trans.shared.b16 {%0,%1,%2,%3}, [%4];"
                 : "=r"(r[0]), "=r"(r[1]), "=r"(r[2]), "=r"(r[3]) : "r"(addr));
}
__device__ __forceinline__ void mma16816(float d[4], const uint32_t a[4],
                                         uint32_t b0, uint32_t b1) {
    asm volatile(
        "mma.sync.aligned.m16n8k16.row.col.f32.bf16.bf16.f32 "
        "{%0,%1,%2,%3}, {%4,%5,%6,%7}, {%8,%9}, {%0,%1,%2,%3};"
        : "+f"(d[0]), "+f"(d[1]), "+f"(d[2]), "+f"(d[3])
        : "r"(a[0]), "r"(a[1]), "r"(a[2]), "r"(a[3]), "r"(b0), "r"(b1));
}
__device__ __forceinline__ void mma16816h(float d[4], const uint32_t a[4],
                                          uint32_t b0, uint32_t b1) {
    asm volatile(
        "mma.sync.aligned.m16n8k16.row.col.f32.f16.f16.f32 "
        "{%0,%1,%2,%3}, {%4,%5,%6,%7}, {%8,%9}, {%0,%1,%2,%3};"
        : "+f"(d[0]), "+f"(d[1]), "+f"(d[2]), "+f"(d[3])
        : "r"(a[0]), "r"(a[1]), "r"(a[2]), "r"(a[3]), "r"(b0), "r"(b1));
}
__device__ __forceinline__ void cpa16(uint32_t dst, const void* src) {
    asm volatile("cp.async.cg.shared.global [%0], [%1], 16;" :: "r"(dst), "l"(src));
}
#define CP_COMMIT() asm volatile("cp.async.commit_group;" ::: "memory")
#define CP_WAIT0()  asm volatile("cp.async.wait_group 0;" ::: "memory")
#define CP_WAIT1()  asm volatile("cp.async.wait_group 1;" ::: "memory")

// fast packed bf16 split: hi = rn(a,b) packed; residuals via bit extraction
__device__ __forceinline__ uint32_t pkbf(float a, float b, float* ra, float* rb) {
    __nv_bfloat162 h2 = __floats2bfloat162_rn(a, b);   // .x = a (low)
    uint32_t u = *reinterpret_cast<uint32_t*>(&h2);
    *ra = a - __uint_as_float(u << 16);
    *rb = b - __uint_as_float(u & 0xffff0000u);
    return u;
}
__device__ __forceinline__ uint32_t pkbf2(float a, float b) {
    __nv_bfloat162 h2 = __floats2bfloat162_rn(a, b);
    return *reinterpret_cast<uint32_t*>(&h2);
}
__device__ __forceinline__ uint32_t pkh2(float a, float b) {
    __half2 h2 = __floats2half2_rn(a, b);              // .x = a (low)
    return *reinterpret_cast<uint32_t*>(&h2);
}

// =================================================================
// K0a: split x -> bf16 hi/lo
// =================================================================
__global__ __launch_bounds__(256) void split_x_kernel(const float* __restrict__ x)
{
    size_t i = ((size_t)blockIdx.x * 256 + threadIdx.x) * 4;
    float4 v = *(const float4*)&x[i];
    float r0, r1, r2, r3;
    uint32_t h01 = pkbf(v.x, v.y, &r0, &r1);
    uint32_t h23 = pkbf(v.z, v.w, &r2, &r3);
    *(uint2*)&g_Xh[i] = make_uint2(h01, h23);
    *(uint2*)&g_Xl[i] = make_uint2(pkbf2(r0, r1), pkbf2(r2, r3));
}

// =================================================================
// K0b: split weights (theta/phi/g -> bf16 hi/lo, W -> fp16 single)
// =================================================================
__global__ __launch_bounds__(256) void split_wts_kernel(
    const float* __restrict__ thw, const float* __restrict__ phw,
    const float* __restrict__ gw,  const float* __restrict__ Ww)
{
    int i = blockIdx.x * 256 + threadIdx.x;   // 0..131071
    int which = i >> 15, j = i & 32767;
    if (which == 3) { g_Whalf[j] = __float2half(Ww[j]); return; }
    float v;
    __nv_bfloat16 *dh, *dl;
    int o;
    if (which == 0)      { v = thw[j]; dh = g_WQh; dl = g_WQl; o = j; }
    else if (which == 1) { v = phw[j]; dh = g_WQh; dl = g_WQl; o = 32768 + j; }
    else                 { v = gw[j];  dh = g_WGh; dl = g_WGl; o = j; }
    __nv_bfloat16 h = __float2bfloat16(v);
    dh[o] = h;
    dl[o] = __float2bfloat16(v - __bfloat162float(h));
}

// =================================================================
// K1a: theta/phi projection (HMMA, bf16 split) -> [b][n][c] hi/lo
// =================================================================
#define PSQ 272
#define PSW 80
#define PJ_XH 0
#define PJ_XL 8704
#define PJ_WH 17408
#define PJ_WL 37888
#define PJ_BUF 58368
#define PJ_BIAS 116736
#define PJ_SMEM 117760

__global__ __launch_bounds__(256, 1) void proj_npos_kernel(
    const float* __restrict__ th_b, const float* __restrict__ ph_b)
{
    extern __shared__ __align__(16) char smem[];
    const uint32_t sb = s2u(smem);
    const int t = threadIdx.x, w = t >> 5, L = t & 31;
    const int g = L >> 2, tc = L & 3;
    const int b = blockIdx.y;
    const int n0 = blockIdx.x * 128;

    float* bias = (float*)(smem + PJ_BIAS);
    bias[t] = (t < 128) ? th_b[t] : ph_b[t - 128];

    const __nv_bfloat16* xh = g_Xh + (size_t)b * CIN * NPOS + n0;
    const __nv_bfloat16* xl = g_Xl + (size_t)b * CIN * NPOS + n0;

    const uint32_t aoff = (uint32_t)(((L & 7) + ((L >> 4) & 1) * 8) * PSQ + 32 * w +
                                     ((L >> 3) & 1) * 16);
    const uint32_t boff = (uint32_t)(((L >> 4) * 8 + (L & 7)) * PSW + ((L >> 3) & 1) * 16);

    float acc[32][4];
    #pragma unroll
    for (int j = 0; j < 32; j++)
        #pragma unroll
        for (int k = 0; k < 4; k++) acc[j][k] = 0.f;

    {
        uint32_t base = sb;
        for (int i = t; i < 512; i += 256) {
            int r = i >> 4, c16 = i & 15;
            uint32_t doff = (uint32_t)(r * PSQ + c16 * 16);
            cpa16(base + PJ_XH + doff, xh + (size_t)r * NPOS + c16 * 8);
            cpa16(base + PJ_XL + doff, xl + (size_t)r * NPOS + c16 * 8);
        }
        for (int i = t; i < 1024; i += 256) {
            int r = i >> 2, c4 = i & 3;
            uint32_t doff = (uint32_t)(r * PSW + c4 * 16);
            cpa16(base + PJ_WH + doff, g_WQh + (size_t)r * CIN + c4 * 8);
            cpa16(base + PJ_WL + doff, g_WQl + (size_t)r * CIN + c4 * 8);
        }
        CP_COMMIT();
    }

    #pragma unroll 1
    for (int ch = 0; ch < 8; ch++) {
        if (ch < 7) {
            int c0 = (ch + 1) * 32;
            uint32_t base = sb + ((ch + 1) & 1) * PJ_BUF;
            for (int i = t; i < 512; i += 256) {
                int r = i >> 4, c16 = i & 15;
                uint32_t doff = (uint32_t)(r * PSQ + c16 * 16);
                cpa16(base + PJ_XH + doff, xh + (size_t)(c0 + r) * NPOS + c16 * 8);
                cpa16(base + PJ_XL + doff, xl + (size_t)(c0 + r) * NPOS + c16 * 8);
            }
            for (int i = t; i < 1024; i += 256) {
                int r = i >> 2, c4 = i & 3;
                uint32_t doff = (uint32_t)(r * PSW + c4 * 16);
                cpa16(base + PJ_WH + doff, g_WQh + (size_t)r * CIN + c0 + c4 * 8);
                cpa16(base + PJ_WL + doff, g_WQl + (size_t)r * CIN + c0 + c4 * 8);
            }
            CP_COMMIT();
            CP_WAIT1();
        } else {
            CP_WAIT0();
        }
        __syncthreads();
        const uint32_t xbase = sb + (ch & 1) * PJ_BUF;
        const uint32_t aB = xbase + PJ_XH + aoff;
        const uint32_t bB = xbase + PJ_WH + boff;
        #pragma unroll
        for (int kk = 0; kk < 2; kk++) {
            uint32_t ah[4], al[4];
            ldsm4t(ah, aB + kk * 16 * PSQ);
            ldsm4t(al, aB + 8704 + kk * 16 * PSQ);
            #pragma unroll
            for (int np = 0; np < 16; np++) {
                uint32_t bh[4], bl[4];
                ldsm4(bh, bB + np * (16 * PSW) + kk * 32);
                ldsm4(bl, bB + 20480 + np * (16 * PSW) + kk * 32);
                mma16816(acc[2 * np],     ah, bh[0], bh[1]);
                mma16816(acc[2 * np + 1], ah, bh[2], bh[3]);
                mma16816(acc[2 * np],     ah, bl[0], bl[1]);
                mma16816(acc[2 * np + 1], ah, bl[2], bl[3]);
                mma16816(acc[2 * np],     al, bh[0], bh[1]);
                mma16816(acc[2 * np + 1], al, bh[2], bh[3]);
            }
        }
        __syncthreads();
    }

    const int nrow = n0 + 16 * w + g;
    const size_t rb0 = ((size_t)b * NPOS + nrow) * CI;
    const size_t rb1 = rb0 + (size_t)8 * CI;
    #pragma unroll
    for (int j = 0; j < 32; j++) {
        int o = 8 * j + 2 * tc;
        float b0 = bias[o], b1 = bias[o + 1];
        __nv_bfloat16 *dh, *dl;
        int c;
        if (o < 128) { dh = g_THh; dl = g_THl; c = o; }
        else         { dh = g_PHh; dl = g_PHl; c = o - 128; }
        float r0, r1;
        uint32_t hp = pkbf(acc[j][0] + b0, acc[j][1] + b1, &r0, &r1);
        uint32_t lp = pkbf2(r0, r1);
        *(uint32_t*)(dh + rb0 + c) = hp;
        *(uint32_t*)(dl + rb0 + c) = lp;
        hp = pkbf(acc[j][2] + b0, acc[j][3] + b1, &r0, &r1);
        lp = pkbf2(r0, r1);
        *(uint32_t*)(dh + rb1 + c) = hp;
        *(uint32_t*)(dl + rb1 + c) = lp;
    }
}

// =================================================================
// K1b: g projection (HMMA, bf16 split compute) -> fp16 single [b][c][n]
// =================================================================
#define PG_XH 0
#define PG_XL 8704
#define PG_WH 17408
#define PG_WL 27648
#define PG_BUF 37888
#define PG_BIAS 75776
#define PG_SMEM 76800

__global__ __launch_bounds__(256, 1) void proj_chan_kernel(const float* __restrict__ g_b)
{
    extern __shared__ __align__(16) char smem[];
    const uint32_t sb = s2u(smem);
    const int t = threadIdx.x, w = t >> 5, L = t & 31;
    const int g = L >> 2, tc = L & 3;
    const int b = blockIdx.y;
    const int n0 = blockIdx.x * 128;

    float* bias = (float*)(smem + PG_BIAS);
    if (t < 128) bias[t] = g_b[t];

    const __nv_bfloat16* xh = g_Xh + (size_t)b * CIN * NPOS + n0;
    const __nv_bfloat16* xl = g_Xl + (size_t)b * CIN * NPOS + n0;

    const uint32_t aoff = (uint32_t)((16 * w + (L & 7) + ((L >> 3) & 1) * 8) * PSW +
                                     (L >> 4) * 16);
    const uint32_t boff = (uint32_t)(((L & 7) + ((L >> 3) & 1) * 8) * PSQ + (L >> 4) * 16);

    float acc[16][4];
    #pragma unroll
    for (int j = 0; j < 16; j++)
        #pragma unroll
        for (int k = 0; k < 4; k++) acc[j][k] = 0.f;

    {
        uint32_t base = sb;
        for (int i = t; i < 512; i += 256) {
            int r = i >> 4, c16 = i & 15;
            uint32_t doff = (uint32_t)(r * PSQ + c16 * 16);
            cpa16(base + PG_XH + doff, xh + (size_t)r * NPOS + c16 * 8);
            cpa16(base + PG_XL + doff, xl + (size_t)r * NPOS + c16 * 8);
        }
        for (int i = t; i < 512; i += 256) {
            int r = i >> 2, c4 = i & 3;
            uint32_t doff = (uint32_t)(r * PSW + c4 * 16);
            cpa16(base + PG_WH + doff, g_WGh + (size_t)r * CIN + c4 * 8);
            cpa16(base + PG_WL + doff, g_WGl + (size_t)r * CIN + c4 * 8);
        }
        CP_COMMIT();
    }

    #pragma unroll 1
    for (int ch = 0; ch < 8; ch++) {
        if (ch < 7) {
            int c0 = (ch + 1) * 32;
            uint32_t base = sb + ((ch + 1) & 1) * PG_BUF;
            for (int i = t; i < 512; i += 256) {
                int r = i >> 4, c16 = i & 15;
                uint32_t doff = (uint32_t)(r * PSQ + c16 * 16);
                cpa16(base + PG_XH + doff, xh + (size_t)(c0 + r) * NPOS + c16 * 8);
                cpa16(base + PG_XL + doff, xl + (size_t)(c0 + r) * NPOS + c16 * 8);
            }
            for (int i = t; i < 512; i += 256) {
                int r = i >> 2, c4 = i & 3;
                uint32_t doff = (uint32_t)(r * PSW + c4 * 16);
                cpa16(base + PG_WH + doff, g_WGh + (size_t)r * CIN + c0 + c4 * 8);
                cpa16(base + PG_WL + doff, g_WGl + (size_t)r * CIN + c0 + c4 * 8);
            }
            CP_COMMIT();
            CP_WAIT1();
        } else {
            CP_WAIT0();
        }
        __syncthreads();
        const uint32_t xbase = sb + (ch & 1) * PG_BUF;
        const uint32_t aB = xbase + PG_WH + aoff;
        const uint32_t bB = xbase + PG_XH + boff;
        #pragma unroll
        for (int kk = 0; kk < 2; kk++) {
            uint32_t ah[4], al[4];
            ldsm4(ah, aB + kk * 32);
            ldsm4(al, aB + 10240 + kk * 32);
            #pragma unroll
            for (int np = 0; np < 8; np++) {
                uint32_t bh[4], bl[4];
                ldsm4t(bh, bB + np * 32 + kk * 16 * PSQ);
                ldsm4t(bl, bB + 8704 + np * 32 + kk * 16 * PSQ);
                mma16816(acc[2 * np],     ah, bh[0], bh[1]);
                mma16816(acc[2 * np + 1], ah, bh[2], bh[3]);
                mma16816(acc[2 * np],     ah, bl[0], bl[1]);
                mma16816(acc[2 * np + 1], ah, bl[2], bl[3]);
                mma16816(acc[2 * np],     al, bh[0], bh[1]);
                mma16816(acc[2 * np + 1], al, bh[2], bh[3]);
            }
        }
        __syncthreads();
    }

    const int o = 16 * w + g;
    const float b0 = bias[o], b8 = bias[o + 8];
    #pragma unroll
    for (int j = 0; j < 16; j++) {
        int n = 16 * (j >> 1) + 8 * (j & 1) + 2 * tc;
        size_t a0 = ((size_t)b * CI + o) * NPOS + n0 + n;
        size_t a8 = a0 + (size_t)8 * NPOS;
        *(uint32_t*)(g_G + a0) = pkh2(acc[j][0] + b0, acc[j][1] + b0);
        *(uint32_t*)(g_G + a8) = pkh2(acc[j][2] + b8, acc[j][3] + b8);
    }
}

// =================================================================
// K2: HMMA attention — QK bf16 3-term, PV fp16 1-term (flash online max),
// W-conv fp16 1-term. One __syncthreads per key-tile.
// =================================================================
#define SQ  272
#define SPG 144
#define SM_QH  0
#define SM_QL  34816
#define SM_K0  69632            // K buf0: hi @0, lo @+17408
#define SM_K1  104448           // K buf1
#define SM_G0  139264           // G buf0 (fp16 single, 18432B)
#define SM_G1  157696           // G buf1
#define SMEM_BYTES 176128
#define SM_WB  69632            // epilogue: W fp16 tile aliases K0

__global__ __launch_bounds__(256, 1) void attn_mma_kernel(const float* __restrict__ W_b)
{
    extern __shared__ __align__(16) char smem[];
    const uint32_t sb = s2u(smem);
    const int t = threadIdx.x, w = t >> 5, L = t & 31;
    const int b = blockIdx.y;
    const int q0 = blockIdx.x * 128;
    const int g  = L >> 2, tc = L & 3;

    const __nv_bfloat16* qh  = g_THh + ((size_t)b * NPOS + q0) * CI;
    const __nv_bfloat16* ql  = g_THl + ((size_t)b * NPOS + q0) * CI;
    const __nv_bfloat16* khb = g_PHh + (size_t)b * NPOS * CI;
    const __nv_bfloat16* klb = g_PHl + (size_t)b * NPOS * CI;
    const __half*        ghb = g_G + (size_t)b * CI * NPOS;

    // prologue: Q, K(0)->buf0, G(0)->buf0
    for (int i = t; i < 2048; i += 256) {
        int r = i >> 4, c16 = i & 15;
        uint32_t doff = (uint32_t)(r * SQ + c16 * 16);
        cpa16(sb + SM_QH + doff, qh + (size_t)r * CI + c16 * 8);
        cpa16(sb + SM_QL + doff, ql + (size_t)r * CI + c16 * 8);
    }
    for (int i = t; i < 1024; i += 256) {
        int r = i >> 4, c16 = i & 15;
        uint32_t doff = (uint32_t)(r * SQ + c16 * 16);
        cpa16(sb + SM_K0 + doff, khb + (size_t)r * CI + c16 * 8);
        cpa16(sb + SM_K0 + 17408 + doff, klb + (size_t)r * CI + c16 * 8);
    }
    for (int i = t; i < 1024; i += 256) {
        int r = i >> 3, c8 = i & 7;
        cpa16(sb + SM_G0 + (uint32_t)(r * SPG + c8 * 16), ghb + (size_t)r * NPOS + c8 * 8);
    }
    CP_COMMIT();

    // per-lane ldmatrix bases
    const int lr = ((L >> 3) & 1) * 8 + (L & 7);
    const int lk = (L >> 4) * 16;
    const int bn = (L >> 4) * 8 + (L & 7);
    const int bk = ((L >> 3) & 1) * 16;

    const uint32_t aQh = sb + SM_QH + (uint32_t)((16 * w + lr) * SQ + lk);
    const uint32_t aQl = aQh + (SM_QL - SM_QH);
    const uint32_t kOff = (uint32_t)(bn * SQ + bk);
    const uint32_t gOff = (uint32_t)(bn * SPG + bk);

    float yacc[16][4];
    #pragma unroll
    for (int n = 0; n < 16; n++)
        #pragma unroll
        for (int j = 0; j < 4; j++) yacc[n][j] = 0.f;
    float ls0 = 0.f, ls1 = 0.f;
    float m0 = -INFINITY, m1 = -INFINITY;

    #pragma unroll 1
    for (int mt = 0; mt < NPOS / 64; mt++) {
        CP_WAIT0();
        __syncthreads();   // K(mt),G(mt) ready; everyone done with prev buffers

        // prefetch K(mt+1), G(mt+1) into alternate buffers
        if (mt < 63) {
            const int m1i = mt * 64 + 64;
            const uint32_t kdst = sb + (((mt + 1) & 1) ? SM_K1 : SM_K0);
            const uint32_t gdst = sb + (((mt + 1) & 1) ? SM_G1 : SM_G0);
            for (int i = t; i < 1024; i += 256) {
                int r = i >> 4, c16 = i & 15;
                uint32_t doff = (uint32_t)(r * SQ + c16 * 16);
                cpa16(kdst + doff, khb + (size_t)(m1i + r) * CI + c16 * 8);
                cpa16(kdst + 17408 + doff, klb + (size_t)(m1i + r) * CI + c16 * 8);
            }
            for (int i = t; i < 1024; i += 256) {
                int r = i >> 3, c8 = i & 7;
                cpa16(gdst + (uint32_t)(r * SPG + c8 * 16),
                      ghb + (size_t)r * NPOS + m1i + c8 * 8);
            }
            CP_COMMIT();
        }

        // ---- QK fused-split (bf16, 3 terms) ----
        const uint32_t bKh = sb + ((mt & 1) ? SM_K1 : SM_K0) + kOff;
        const uint32_t bKl = bKh + 17408;
        float acc[8][4];
        #pragma unroll
        for (int n = 0; n < 8; n++)
            #pragma unroll
            for (int j = 0; j < 4; j++) acc[n][j] = 0.f;
        #pragma unroll
        for (int kk = 0; kk < 8; kk++) {
            uint32_t ah[4], al[4];
            ldsm4(ah, aQh + kk * 32);
            ldsm4(al, aQl + kk * 32);
            #pragma unroll
            for (int np = 0; np < 4; np++) {
                uint32_t bh[4], bl[4];
                ldsm4(bh, bKh + np * (16 * SQ) + kk * 32);
                ldsm4(bl, bKl + np * (16 * SQ) + kk * 32);
                mma16816(acc[2 * np],     ah, bh[0], bh[1]);
                mma16816(acc[2 * np + 1], ah, bh[2], bh[3]);
                mma16816(acc[2 * np],     ah, bl[0], bl[1]);
                mma16816(acc[2 * np + 1], ah, bl[2], bl[3]);
                mma16816(acc[2 * np],     al, bh[0], bh[1]);
                mma16816(acc[2 * np + 1], al, bh[2], bh[3]);
            }
        }

        // ---- flash online-max softmax ----
        float tm0 = -INFINITY, tm1 = -INFINITY;
        #pragma unroll
        for (int n = 0; n < 8; n++) {
            tm0 = fmaxf(tm0, fmaxf(acc[n][0], acc[n][1]));
            tm1 = fmaxf(tm1, fmaxf(acc[n][2], acc[n][3]));
        }
        tm0 = fmaxf(tm0, __shfl_xor_sync(0xffffffffu, tm0, 1));
        tm0 = fmaxf(tm0, __shfl_xor_sync(0xffffffffu, tm0, 2));
        tm1 = fmaxf(tm1, __shfl_xor_sync(0xffffffffu, tm1, 1));
        tm1 = fmaxf(tm1, __shfl_xor_sync(0xffffffffu, tm1, 2));
        float mn0 = fmaxf(m0, tm0), mn1 = fmaxf(m1, tm1);
        float al0 = __expf(m0 - mn0), al1 = __expf(m1 - mn1);
        m0 = mn0; m1 = mn1;
        ls0 *= al0; ls1 *= al1;
        #pragma unroll
        for (int n = 0; n < 16; n++) {
            yacc[n][0] *= al0; yacc[n][1] *= al0;
            yacc[n][2] *= al1; yacc[n][3] *= al1;
        }

        // exp + pack P directly into fp16 A-fragments
        uint32_t pf[4][4];
        #pragma unroll
        for (int n = 0; n < 8; n++) {
            float p0 = __expf(acc[n][0] - m0);
            float p1 = __expf(acc[n][1] - m0);
            float p2 = __expf(acc[n][2] - m1);
            float p3 = __expf(acc[n][3] - m1);
            ls0 += p0 + p1;
            ls1 += p2 + p3;
            int kk = n >> 1, e = (n & 1) * 2;
            pf[kk][e]     = pkh2(p0, p1);
            pf[kk][e + 1] = pkh2(p2, p3);
        }

        // ---- PV (fp16 single term) ----
        const uint32_t bG = sb + ((mt & 1) ? SM_G1 : SM_G0) + gOff;
        #pragma unroll
        for (int kk = 0; kk < 4; kk++) {
            #pragma unroll
            for (int np = 0; np < 8; np++) {
                uint32_t bh[4];
                ldsm4(bh, bG + np * (16 * SPG) + kk * 32);
                mma16816h(yacc[2 * np],     pf[kk], bh[0], bh[1]);
                mma16816h(yacc[2 * np + 1], pf[kk], bh[2], bh[3]);
            }
        }
    }

    // ---- finalize row sums ----
    ls0 += __shfl_xor_sync(0xffffffffu, ls0, 1);
    ls0 += __shfl_xor_sync(0xffffffffu, ls0, 2);
    ls1 += __shfl_xor_sync(0xffffffffu, ls1, 1);
    ls1 += __shfl_xor_sync(0xffffffffu, ls1, 2);

    // ---- normalize Y, pack into fp16 W-conv A-fragments (k = channel) ----
    uint32_t yf[8][4];
    {
        float rv0 = 1.f / ls0, rv1 = 1.f / ls1;
        #pragma unroll
        for (int n = 0; n < 16; n++) {
            int kk = n >> 1, e = (n & 1) * 2;
            yf[kk][e]     = pkh2(yacc[n][0] * rv0, yacc[n][1] * rv0);
            yf[kk][e + 1] = pkh2(yacc[n][2] * rv1, yacc[n][3] * rv1);
        }
    }

    // ---- WY = W_w @ Y + W_b : fp16 single term, two 128-channel halves ----
    const uint32_t bW = sb + SM_WB + (uint32_t)(bn * SQ + bk);
    float* WYb = g_WY + (size_t)b * CIN * NPOS + q0;

    #pragma unroll 1
    for (int h = 0; h < 2; h++) {
        __syncthreads();   // K/G reads done (h=0) / prev W reads done (h=1)
        const __half* wsrc = g_Whalf + (size_t)h * 128 * CI;
        for (int i = t; i < 2048; i += 256) {
            int r = i >> 4, c16 = i & 15;
            *(uint4*)(smem + SM_WB + (uint32_t)(r * SQ + c16 * 16)) =
                *(const uint4*)(wsrc + (size_t)r * CI + c16 * 8);
        }
        __syncthreads();

        float wacc[16][4];
        #pragma unroll
        for (int n = 0; n < 16; n++)
            #pragma unroll
            for (int j = 0; j < 4; j++) wacc[n][j] = 0.f;

        #pragma unroll
        for (int kk = 0; kk < 8; kk++) {
            #pragma unroll
            for (int np = 0; np < 8; np++) {
                uint32_t bh[4];
                ldsm4(bh, bW + np * (16 * SQ) + kk * 32);
                mma16816h(wacc[2 * np],     yf[kk], bh[0], bh[1]);
                mma16816h(wacc[2 * np + 1], yf[kk], bh[2], bh[3]);
            }
        }

        #pragma unroll
        for (int n = 0; n < 16; n++) {
            int o = h * 128 + 8 * n + 2 * tc;
            float b0 = __ldg(&W_b[o]);
            float b1 = __ldg(&W_b[o + 1]);
            int r0 = 16 * w + g;
            WYb[(size_t)o * NPOS + r0]           = wacc[n][0] + b0;
            WYb[(size_t)(o + 1) * NPOS + r0]     = wacc[n][1] + b1;
            WYb[(size_t)o * NPOS + r0 + 8]       = wacc[n][2] + b0;
            WYb[(size_t)(o + 1) * NPOS + r0 + 8] = wacc[n][3] + b1;
        }
    }
}

// =================================================================
// K3: BN statistics — partial pass + finalize
// =================================================================
__global__ __launch_bounds__(256) void stats_part_kernel()
{
    const int c = blockIdx.x;
    const int s = blockIdx.y;
    const int t = threadIdx.x;
    float sm = 0.f, ss = 0.f;
    for (int b = 2 * s; b < 2 * s + 2; b++) {
        const float* p = g_WY + ((size_t)b * CIN + c) * NPOS;
        for (int i = t; i < NPOS / 4; i += 256) {
            float4 v = *(const float4*)&p[4 * i];
            sm += v.x + v.y + v.z + v.w;
            ss += v.x * v.x + v.y * v.y + v.z * v.z + v.w * v.w;
        }
    }
    __shared__ float rs[256], rss[256];
    rs[t] = sm; rss[t] = ss;
    __syncthreads();
    for (int o = 128; o > 0; o >>= 1) {
        if (t < o) { rs[t] += rs[t + o]; rss[t] += rss[t + o]; }
        __syncthreads();
    }
    if (t == 0) {
        g_ps[s * CIN + c]  = rs[0];
        g_pss[s * CIN + c] = rss[0];
    }
}

__global__ __launch_bounds__(256) void stats_fin_kernel()
{
    const int c = threadIdx.x;
    float sm = g_ps[c] + g_ps[CIN + c] + g_ps[2 * CIN + c] + g_ps[3 * CIN + c];
    float ss = g_pss[c] + g_pss[CIN + c] + g_pss[2 * CIN + c] + g_pss[3 * CIN + c];
    const float inv = 1.f / (float)(BATCH * NPOS);
    float mean = sm * inv;
    float var  = ss * inv - mean * mean;
    g_mean[c] = mean;
    g_rstd[c] = rsqrtf(var + 1e-5f);
}

// =================================================================
// K4: z = (wy - mean)*rstd*gamma + beta + x
// =================================================================
__global__ __launch_bounds__(256) void final_kernel(
    const float* __restrict__ x,
    const float* __restrict__ gamma, const float* __restrict__ beta,
    float* __restrict__ z)
{
    size_t i4 = (size_t)blockIdx.x * 256 + threadIdx.x;
    size_t i  = i4 * 4;
    int c = (int)((i >> 12) & 255);
    float m = g_mean[c], r = g_rstd[c], ga = gamma[c], be = beta[c];
    float4 wy = *(const float4*)&g_WY[i];
    float4 xv = *(const float4*)&x[i];
    float4 o;
    o.x = (wy.x - m) * r * ga + be + xv.x;
    o.y = (wy.y - m) * r * ga + be + xv.y;
    o.z = (wy.z - m) * r * ga + be + xv.z;
    o.w = (wy.w - m) * r * ga + be + xv.w;
    *(float4*)&z[i] = o;
}

// =================================================================
extern "C" void kernel_launch(void* const* d_in, const int* in_sizes, int n_in,
                              void* d_out, int out_size)
{
    const float* x       = (const float*)d_in[0];
    const float* g_w     = (const float*)d_in[1];
    const float* g_b     = (const float*)d_in[2];
    const float* theta_w = (const float*)d_in[3];
    const float* theta_b = (const float*)d_in[4];
    const float* phi_w   = (const float*)d_in[5];
    const float* phi_b   = (const float*)d_in[6];
    const float* W_w     = (const float*)d_in[7];
    const float* W_b     = (const float*)d_in[8];
    const float* bn_g    = (const float*)d_in[9];
    const float* bn_b    = (const float*)d_in[10];
    float* z = (float*)d_out;

    cudaFuncSetAttribute(proj_npos_kernel, cudaFuncAttributeMaxDynamicSharedMemorySize, PJ_SMEM);
    cudaFuncSetAttribute(proj_chan_kernel, cudaFuncAttributeMaxDynamicSharedMemorySize, PG_SMEM);
    cudaFuncSetAttribute(attn_mma_kernel,  cudaFuncAttributeMaxDynamicSharedMemorySize, SMEM_BYTES);

    split_x_kernel<<<8192, 256>>>(x);
    split_wts_kernel<<<512, 256>>>(theta_w, phi_w, g_w, W_w);
    proj_npos_kernel<<<dim3(32, 8), 256, PJ_SMEM>>>(theta_b, phi_b);
    proj_chan_kernel<<<dim3(32, 8), 256, PG_SMEM>>>(g_b);
    attn_mma_kernel<<<dim3(32, 8), 256, SMEM_BYTES>>>(W_b);
    stats_part_kernel<<<dim3(256, 4), 256>>>();
    stats_fin_kernel<<<1, 256>>>();
    final_kernel<<<8192, 256>>>(x, bn_g, bn_b, z);
}